// round 2
// baseline (speedup 1.0000x reference)
#include <cuda_runtime.h>
#include <math.h>

#define SEQ 2048
#define DMODEL 2048
#define NH 16
#define DH 128
#define DFF 8192
#define BOTTLE 1088   /* BACKGROUND_LEN + STYLE_VECS_LEN */
#define BG 1024       /* BACKGROUND_LEN */

// -------- scratch (no allocations allowed) --------
__device__ float g_xn[(size_t)SEQ * DMODEL];
__device__ float g_q[(size_t)SEQ * DMODEL];
__device__ float g_k[(size_t)SEQ * DMODEL];
__device__ float g_v[(size_t)SEQ * DMODEL];
__device__ float g_att[(size_t)SEQ * DMODEL];
__device__ float g_ff[(size_t)SEQ * DFF];
__device__ float g_logits[(size_t)NH * SEQ * SEQ];

// -------- reductions --------
__device__ __forceinline__ float blockReduceSum(float val) {
    __shared__ float sh[8];
    __shared__ float res;
    int lane = threadIdx.x & 31, w = threadIdx.x >> 5;
    #pragma unroll
    for (int o = 16; o > 0; o >>= 1) val += __shfl_xor_sync(0xffffffffu, val, o);
    if (lane == 0) sh[w] = val;
    __syncthreads();
    if (threadIdx.x == 0) {
        float s = 0.f;
        #pragma unroll
        for (int i = 0; i < 8; i++) s += sh[i];
        res = s;
    }
    __syncthreads();
    float r = res;
    __syncthreads();
    return r;
}

__device__ __forceinline__ float blockReduceMax(float val) {
    __shared__ float sh[8];
    __shared__ float res;
    int lane = threadIdx.x & 31, w = threadIdx.x >> 5;
    #pragma unroll
    for (int o = 16; o > 0; o >>= 1) val = fmaxf(val, __shfl_xor_sync(0xffffffffu, val, o));
    if (lane == 0) sh[w] = val;
    __syncthreads();
    if (threadIdx.x == 0) {
        float s = -INFINITY;
        #pragma unroll
        for (int i = 0; i < 8; i++) s = fmaxf(s, sh[i]);
        res = s;
    }
    __syncthreads();
    float r = res;
    __syncthreads();
    return r;
}

// -------- LayerNorm --------
__global__ void ln_kernel(const float* __restrict__ x, const float* __restrict__ sc,
                          const float* __restrict__ of, float* __restrict__ out) {
    int row = blockIdx.x;
    const float* xr = x + (size_t)row * DMODEL;
    float* o = out + (size_t)row * DMODEL;
    float s = 0.f, s2 = 0.f;
    for (int i = threadIdx.x; i < DMODEL; i += blockDim.x) {
        float v = xr[i];
        s += v; s2 += v * v;
    }
    s  = blockReduceSum(s);
    s2 = blockReduceSum(s2);
    float mean = s / DMODEL;
    float var  = s2 / DMODEL - mean * mean;
    float r = rsqrtf(var + 1e-5f);
    for (int i = threadIdx.x; i < DMODEL; i += blockDim.x)
        o[i] = sc[i] * r * (xr[i] - mean) + of[i];
}

// -------- RoPE (in place on q,k) --------
__global__ void rope_kernel(float* __restrict__ q, float* __restrict__ k) {
    int idx = blockIdx.x * blockDim.x + threadIdx.x;  // over SEQ * DMODEL/2 pairs
    if (idx >= SEQ * (DMODEL / 2)) return;
    int t = idx / (DMODEL / 2);
    int r = idx % (DMODEL / 2);
    int h = r / (DH / 2);
    int i = r % (DH / 2);
    float inv = powf(10000.0f, -(float)(2 * i) / (float)DH);
    float ang = (float)t * inv;
    float s, c;
    sincosf(ang, &s, &c);
    size_t base = (size_t)t * DMODEL + (size_t)h * DH + 2 * i;
    float q0 = q[base], q1 = q[base + 1];
    q[base]     = q0 * c - q1 * s;
    q[base + 1] = q1 * c + q0 * s;
    float k0 = k[base], k1 = k[base + 1];
    k[base]     = k0 * c - k1 * s;
    k[base + 1] = k1 * c + k0 * s;
}

// -------- GELU (tanh approx == jax.nn.gelu default) --------
__device__ __forceinline__ float gelu_f(float x) {
    float x3 = x * x * x;
    return 0.5f * x * (1.0f + tanhf(0.7978845608028654f * (x + 0.044715f * x3)));
}

// -------- generic NN SGEMM: C = A(MxK,lda) @ B(KxN,ldb) --------
// EPI 0: C = acc
// EPI 1: C = gelu(acc + bias[n])
// EPI 2: C = C + acc + bias[n]     (residual accumulate)
template <int EPI>
__global__ __launch_bounds__(256)
void gemm_nn(const float* __restrict__ A, const float* __restrict__ B,
             const float* __restrict__ bias, float* __restrict__ C,
             int M, int N, int K, int lda, int ldb, int ldc) {
    __shared__ float As[8][128];
    __shared__ float Bs[8][128];
    int t = threadIdx.x;
    int m0 = blockIdx.y * 128, n0 = blockIdx.x * 128;
    int aRow = t >> 1, aCol = (t & 1) * 4;
    int bRow = t >> 5, bCol = (t & 31) * 4;
    const float* Ap = A + (size_t)(m0 + aRow) * lda + aCol;
    const float* Bp = B + (size_t)bRow * ldb + n0 + bCol;
    float acc[8][8];
    #pragma unroll
    for (int i = 0; i < 8; i++)
        #pragma unroll
        for (int j = 0; j < 8; j++) acc[i][j] = 0.f;
    int ty = t >> 4, tx = t & 15;

    for (int k0 = 0; k0 < K; k0 += 8) {
        float4 a = *(const float4*)(Ap + k0);
        As[aCol + 0][aRow] = a.x;
        As[aCol + 1][aRow] = a.y;
        As[aCol + 2][aRow] = a.z;
        As[aCol + 3][aRow] = a.w;
        float4 b = *(const float4*)(Bp + (size_t)k0 * ldb);
        *(float4*)&Bs[bRow][bCol] = b;
        __syncthreads();
        #pragma unroll
        for (int k = 0; k < 8; k++) {
            float4 a0 = *(float4*)&As[k][ty * 8];
            float4 a1 = *(float4*)&As[k][ty * 8 + 4];
            float4 b0 = *(float4*)&Bs[k][tx * 8];
            float4 b1 = *(float4*)&Bs[k][tx * 8 + 4];
            float ar[8] = {a0.x, a0.y, a0.z, a0.w, a1.x, a1.y, a1.z, a1.w};
            float br[8] = {b0.x, b0.y, b0.z, b0.w, b1.x, b1.y, b1.z, b1.w};
            #pragma unroll
            for (int i = 0; i < 8; i++)
                #pragma unroll
                for (int j = 0; j < 8; j++) acc[i][j] += ar[i] * br[j];
        }
        __syncthreads();
    }

    #pragma unroll
    for (int i = 0; i < 8; i++) {
        int m = m0 + ty * 8 + i;
        #pragma unroll
        for (int j = 0; j < 8; j++) {
            int n = n0 + tx * 8 + j;
            float v = acc[i][j];
            size_t idx = (size_t)m * ldc + n;
            if (EPI == 0) {
                C[idx] = v;
            } else if (EPI == 1) {
                C[idx] = gelu_f(v + bias[n]);
            } else {
                C[idx] = C[idx] + v + bias[n];
            }
        }
    }
}

// -------- QK^T per head with mask/bias/scale epilogue (NT gemm, K = DH = 128) --------
__global__ __launch_bounds__(256)
void qk_kernel(const float* __restrict__ q, const float* __restrict__ k,
               const float* __restrict__ attn_bias, float* __restrict__ logits) {
    int h = blockIdx.z;
    const float* A = q + (size_t)h * DH;
    const float* B = k + (size_t)h * DH;
    float* Cl = logits + (size_t)h * SEQ * SEQ;
    __shared__ float As[8][128];
    __shared__ float Bs[8][128];
    int t = threadIdx.x;
    int m0 = blockIdx.y * 128, n0 = blockIdx.x * 128;
    int aRow = t >> 1, aCol = (t & 1) * 4;
    float acc[8][8];
    #pragma unroll
    for (int i = 0; i < 8; i++)
        #pragma unroll
        for (int j = 0; j < 8; j++) acc[i][j] = 0.f;
    int ty = t >> 4, tx = t & 15;

    for (int k0 = 0; k0 < DH; k0 += 8) {
        float4 a = *(const float4*)(A + (size_t)(m0 + aRow) * DMODEL + k0 + aCol);
        As[aCol + 0][aRow] = a.x;
        As[aCol + 1][aRow] = a.y;
        As[aCol + 2][aRow] = a.z;
        As[aCol + 3][aRow] = a.w;
        float4 b = *(const float4*)(B + (size_t)(n0 + aRow) * DMODEL + k0 + aCol);
        Bs[aCol + 0][aRow] = b.x;
        Bs[aCol + 1][aRow] = b.y;
        Bs[aCol + 2][aRow] = b.z;
        Bs[aCol + 3][aRow] = b.w;
        __syncthreads();
        #pragma unroll
        for (int k = 0; k < 8; k++) {
            float4 a0 = *(float4*)&As[k][ty * 8];
            float4 a1 = *(float4*)&As[k][ty * 8 + 4];
            float4 b0 = *(float4*)&Bs[k][tx * 8];
            float4 b1 = *(float4*)&Bs[k][tx * 8 + 4];
            float ar[8] = {a0.x, a0.y, a0.z, a0.w, a1.x, a1.y, a1.z, a1.w};
            float br[8] = {b0.x, b0.y, b0.z, b0.w, b1.x, b1.y, b1.z, b1.w};
            #pragma unroll
            for (int i = 0; i < 8; i++)
                #pragma unroll
                for (int j = 0; j < 8; j++) acc[i][j] += ar[i] * br[j];
        }
        __syncthreads();
    }

    const float scale = 0.08838834764831845f;  // 1/sqrt(128)
    #pragma unroll
    for (int i = 0; i < 8; i++) {
        int m = m0 + ty * 8 + i;
        #pragma unroll
        for (int j = 0; j < 8; j++) {
            int n = n0 + tx * 8 + j;
            bool allowed = (n <= m) && !((m >= BOTTLE) && (n < BG));
            float v = acc[i][j] * scale + (allowed ? 0.0f : -1e10f)
                    + attn_bias[(size_t)m * SEQ + n];
            Cl[(size_t)m * SEQ + n] = v;
        }
    }
}

// -------- row softmax over logits (in place), one block per (h, t) row --------
__global__ void softmax_kernel(float* __restrict__ logits) {
    size_t row = blockIdx.x;
    float* p = logits + row * SEQ;
    float mx = -INFINITY;
    for (int i = threadIdx.x; i < SEQ; i += blockDim.x) mx = fmaxf(mx, p[i]);
    mx = blockReduceMax(mx);
    float sum = 0.f;
    for (int i = threadIdx.x; i < SEQ; i += blockDim.x) {
        float e = __expf(p[i] - mx);
        p[i] = e;
        sum += e;
    }
    sum = blockReduceSum(sum);
    float inv = 1.0f / sum;
    for (int i = threadIdx.x; i < SEQ; i += blockDim.x) p[i] *= inv;
}

extern "C" void kernel_launch(void* const* d_in, const int* in_sizes, int n_in,
                              void* d_out, int out_size) {
    (void)in_sizes; (void)n_in; (void)out_size;
    const float* x         = (const float*)d_in[0];
    const float* attn_bias = (const float*)d_in[1];
    const float* ln_scale  = (const float*)d_in[2];
    const float* ln_offset = (const float*)d_in[3];
    const float* Wq = (const float*)d_in[4];
    const float* Wk = (const float*)d_in[5];
    const float* Wv = (const float*)d_in[6];
    const float* Wo = (const float*)d_in[7];
    const float* W1 = (const float*)d_in[8];
    const float* b1 = (const float*)d_in[9];
    const float* W2 = (const float*)d_in[10];
    const float* b2 = (const float*)d_in[11];
    float* out = (float*)d_out;

    float *xn, *q, *k, *v, *att, *ff, *logits;
    cudaGetSymbolAddress((void**)&xn,     g_xn);
    cudaGetSymbolAddress((void**)&q,      g_q);
    cudaGetSymbolAddress((void**)&k,      g_k);
    cudaGetSymbolAddress((void**)&v,      g_v);
    cudaGetSymbolAddress((void**)&att,    g_att);
    cudaGetSymbolAddress((void**)&ff,     g_ff);
    cudaGetSymbolAddress((void**)&logits, g_logits);

    // 1. LayerNorm
    ln_kernel<<<SEQ, 256>>>(x, ln_scale, ln_offset, xn);

    // 2. QKV projections
    dim3 g16(DMODEL / 128, SEQ / 128);
    gemm_nn<0><<<g16, 256>>>(xn, Wq, nullptr, q, SEQ, DMODEL, DMODEL, DMODEL, DMODEL, DMODEL);
    gemm_nn<0><<<g16, 256>>>(xn, Wk, nullptr, k, SEQ, DMODEL, DMODEL, DMODEL, DMODEL, DMODEL);
    gemm_nn<0><<<g16, 256>>>(xn, Wv, nullptr, v, SEQ, DMODEL, DMODEL, DMODEL, DMODEL, DMODEL);

    // 3. RoPE
    rope_kernel<<<(SEQ * (DMODEL / 2) + 255) / 256, 256>>>(q, k);

    // 4. logits = q k^T / sqrt(dh) + mask + attn_bias
    qk_kernel<<<dim3(SEQ / 128, SEQ / 128, NH), 256>>>(q, k, attn_bias, logits);

    // 5. softmax
    softmax_kernel<<<NH * SEQ, 256>>>(logits);

    // 6. attn_vec = weights @ v (per head)
    for (int h = 0; h < NH; h++) {
        gemm_nn<0><<<dim3(1, SEQ / 128), 256>>>(
            logits + (size_t)h * SEQ * SEQ, v + (size_t)h * DH, nullptr,
            att + (size_t)h * DH, SEQ, DH, SEQ, SEQ, DMODEL, DMODEL);
    }

    // 7. attn_out = attn_vec @ Wo  -> writes d_out
    gemm_nn<0><<<g16, 256>>>(att, Wo, nullptr, out, SEQ, DMODEL, DMODEL, DMODEL, DMODEL, DMODEL);

    // 8. ff = gelu(xn @ W1 + b1)
    gemm_nn<1><<<dim3(DFF / 128, SEQ / 128), 256>>>(xn, W1, b1, ff, SEQ, DFF, DMODEL, DMODEL, DFF, DFF);

    // 9. out += ff @ W2 + b2
    gemm_nn<2><<<g16, 256>>>(ff, W2, b2, out, SEQ, DMODEL, DFF, DFF, DMODEL, DMODEL);
}

// round 3
// speedup vs baseline: 3.1640x; 3.1640x over previous
#include <cuda_runtime.h>
#include <math.h>
#include <stdint.h>

#define SEQ 2048
#define DMODEL 2048
#define NH 16
#define DH 128
#define DFF 8192
#define BOTTLE 1088   /* BACKGROUND_LEN + STYLE_VECS_LEN */
#define BG 1024       /* BACKGROUND_LEN */

// -------- scratch (no allocations allowed) --------
__device__ float g_xn[(size_t)SEQ * DMODEL];
__device__ float g_q[(size_t)SEQ * DMODEL];
__device__ float g_k[(size_t)SEQ * DMODEL];
__device__ float g_v[(size_t)SEQ * DMODEL];
__device__ float g_att[(size_t)SEQ * DMODEL];
__device__ float g_ff[(size_t)SEQ * DFF];
__device__ float g_logits[(size_t)NH * SEQ * SEQ];

// -------- reductions --------
__device__ __forceinline__ float blockReduceSum(float val) {
    __shared__ float sh[8];
    __shared__ float res;
    int lane = threadIdx.x & 31, w = threadIdx.x >> 5;
    #pragma unroll
    for (int o = 16; o > 0; o >>= 1) val += __shfl_xor_sync(0xffffffffu, val, o);
    if (lane == 0) sh[w] = val;
    __syncthreads();
    if (threadIdx.x == 0) {
        float s = 0.f;
        #pragma unroll
        for (int i = 0; i < 8; i++) s += sh[i];
        res = s;
    }
    __syncthreads();
    float r = res;
    __syncthreads();
    return r;
}

__device__ __forceinline__ float blockReduceMax(float val) {
    __shared__ float sh[8];
    __shared__ float res;
    int lane = threadIdx.x & 31, w = threadIdx.x >> 5;
    #pragma unroll
    for (int o = 16; o > 0; o >>= 1) val = fmaxf(val, __shfl_xor_sync(0xffffffffu, val, o));
    if (lane == 0) sh[w] = val;
    __syncthreads();
    if (threadIdx.x == 0) {
        float s = -INFINITY;
        #pragma unroll
        for (int i = 0; i < 8; i++) s = fmaxf(s, sh[i]);
        res = s;
    }
    __syncthreads();
    float r = res;
    __syncthreads();
    return r;
}

// -------- LayerNorm --------
__global__ void ln_kernel(const float* __restrict__ x, const float* __restrict__ sc,
                          const float* __restrict__ of, float* __restrict__ out) {
    int row = blockIdx.x;
    const float* xr = x + (size_t)row * DMODEL;
    float* o = out + (size_t)row * DMODEL;
    float s = 0.f, s2 = 0.f;
    for (int i = threadIdx.x; i < DMODEL; i += blockDim.x) {
        float v = xr[i];
        s += v; s2 += v * v;
    }
    s  = blockReduceSum(s);
    s2 = blockReduceSum(s2);
    float mean = s / DMODEL;
    float var  = s2 / DMODEL - mean * mean;
    float r = rsqrtf(var + 1e-5f);
    for (int i = threadIdx.x; i < DMODEL; i += blockDim.x)
        o[i] = sc[i] * r * (xr[i] - mean) + of[i];
}

// -------- RoPE (in place on q,k) --------
__global__ void rope_kernel(float* __restrict__ q, float* __restrict__ k) {
    int idx = blockIdx.x * blockDim.x + threadIdx.x;  // over SEQ * DMODEL/2 pairs
    if (idx >= SEQ * (DMODEL / 2)) return;
    int t = idx / (DMODEL / 2);
    int r = idx % (DMODEL / 2);
    int h = r / (DH / 2);
    int i = r % (DH / 2);
    float inv = powf(10000.0f, -(float)(2 * i) / (float)DH);
    float ang = (float)t * inv;
    float s, c;
    sincosf(ang, &s, &c);
    size_t base = (size_t)t * DMODEL + (size_t)h * DH + 2 * i;
    float q0 = q[base], q1 = q[base + 1];
    q[base]     = q0 * c - q1 * s;
    q[base + 1] = q1 * c + q0 * s;
    float k0 = k[base], k1 = k[base + 1];
    k[base]     = k0 * c - k1 * s;
    k[base + 1] = k1 * c + k0 * s;
}

// -------- GELU (tanh approx == jax.nn.gelu default) --------
__device__ __forceinline__ float gelu_f(float x) {
    float x3 = x * x * x;
    return 0.5f * x * (1.0f + tanhf(0.7978845608028654f * (x + 0.044715f * x3)));
}

// -------- tf32 helpers --------
__device__ __forceinline__ uint32_t f2tf32(float f) {
    uint32_t u;
    asm("cvt.rna.tf32.f32 %0, %1;" : "=r"(u) : "f"(f));
    return u;
}
__device__ __forceinline__ float4 cvt4(float4 v) {
    float4 r;
    r.x = __uint_as_float(f2tf32(v.x));
    r.y = __uint_as_float(f2tf32(v.y));
    r.z = __uint_as_float(f2tf32(v.z));
    r.w = __uint_as_float(f2tf32(v.w));
    return r;
}
__device__ __forceinline__ void mma_tf32(float c[4], const uint32_t a[4], const uint32_t b[2]) {
    asm volatile(
        "mma.sync.aligned.m16n8k8.row.col.f32.tf32.tf32.f32 "
        "{%0,%1,%2,%3}, {%4,%5,%6,%7}, {%8,%9}, {%0,%1,%2,%3};\n"
        : "+f"(c[0]), "+f"(c[1]), "+f"(c[2]), "+f"(c[3])
        : "r"(a[0]), "r"(a[1]), "r"(a[2]), "r"(a[3]), "r"(b[0]), "r"(b[1]));
}

// ============ TF32 tensor-core GEMM ============
// C[M,N] = A[M,K] @ op(B), op(B) = B[K,N] (TRANS_B=0) or B[N,K]^T (TRANS_B=1)
// Block tile 128x128, BK=16, 8 warps of 64x32. Batched over grid.z.
// EPI 0: C = acc
// EPI 1: C = gelu(acc + bias[n])
// EPI 2: C = C + acc + bias[n]
// EPI 3: C = acc*1/sqrt(DH) + causal/bottleneck mask + bias[m*SEQ+n]  (attn logits)
template <int TRANS_B, int EPI>
__global__ __launch_bounds__(256)
void mma_gemm(const float* __restrict__ A, const float* __restrict__ B,
              const float* __restrict__ bias, float* __restrict__ C,
              int M, int N, int K, int lda, int ldb, int ldc,
              size_t sA, size_t sB, size_t sC) {
    constexpr int BK = 16;
    __shared__ float As[2][128][20];
    constexpr int BY = TRANS_B ? 128 : BK;
    constexpr int BX = TRANS_B ? 20  : 136;
    __shared__ float Bs[2][BY][BX];

    int z = blockIdx.z;
    A += (size_t)z * sA;
    B += (size_t)z * sB;
    C += (size_t)z * sC;

    int t = threadIdx.x;
    int m0 = blockIdx.y * 128, n0 = blockIdx.x * 128;
    int lane = t & 31, warp = t >> 5;
    int wm = (warp >> 2) * 64;    // 0 or 64
    int wn = (warp & 3) * 32;     // 0,32,64,96
    int gid = lane >> 2, t4 = lane & 3;

    float c[4][4][4];
    #pragma unroll
    for (int f = 0; f < 4; f++)
        #pragma unroll
        for (int g = 0; g < 4; g++)
            #pragma unroll
            for (int e = 0; e < 4; e++) c[f][g][e] = 0.f;

    // loader indexing
    int aRow = t >> 2;            // 0..63 ; second load at +64
    int aKv  = (t & 3) * 4;       // k offset (0,4,8,12)
    int bK   = t >> 5;            // 0..7   ; second at +8     (NN)
    int bNv  = (t & 31) * 4;      // n offset                   (NN)

    float4 ra[2], rb[2];
    int nt = K / BK;

    auto ldgA = [&](int k0) {
        const float* p = A + (size_t)(m0 + aRow) * lda + k0 + aKv;
        ra[0] = *(const float4*)p;
        ra[1] = *(const float4*)(p + (size_t)64 * lda);
    };
    auto ldgB = [&](int k0) {
        if (TRANS_B) {
            const float* p = B + (size_t)(n0 + aRow) * ldb + k0 + aKv;
            rb[0] = *(const float4*)p;
            rb[1] = *(const float4*)(p + (size_t)64 * ldb);
        } else {
            const float* p = B + (size_t)(k0 + bK) * ldb + n0 + bNv;
            rb[0] = *(const float4*)p;
            rb[1] = *(const float4*)(p + (size_t)8 * ldb);
        }
    };
    auto stsA = [&](int s) {
        *(float4*)&As[s][aRow][aKv]      = cvt4(ra[0]);
        *(float4*)&As[s][aRow + 64][aKv] = cvt4(ra[1]);
    };
    auto stsB = [&](int s) {
        if (TRANS_B) {
            *(float4*)&Bs[s][aRow][aKv]      = cvt4(rb[0]);
            *(float4*)&Bs[s][aRow + 64][aKv] = cvt4(rb[1]);
        } else {
            *(float4*)&Bs[s][bK][bNv]     = cvt4(rb[0]);
            *(float4*)&Bs[s][bK + 8][bNv] = cvt4(rb[1]);
        }
    };

    ldgA(0); ldgB(0);
    stsA(0); stsB(0);
    __syncthreads();

    for (int kt = 0; kt < nt; kt++) {
        int s = kt & 1;
        if (kt + 1 < nt) { ldgA((kt + 1) * BK); ldgB((kt + 1) * BK); }

        #pragma unroll
        for (int kk = 0; kk < BK; kk += 8) {
            uint32_t af[4][4];
            #pragma unroll
            for (int f = 0; f < 4; f++) {
                int mr = wm + f * 16 + gid;
                af[f][0] = __float_as_uint(As[s][mr][kk + t4]);
                af[f][1] = __float_as_uint(As[s][mr + 8][kk + t4]);
                af[f][2] = __float_as_uint(As[s][mr][kk + 4 + t4]);
                af[f][3] = __float_as_uint(As[s][mr + 8][kk + 4 + t4]);
            }
            uint32_t bf[4][2];
            #pragma unroll
            for (int g = 0; g < 4; g++) {
                int nc = wn + g * 8 + gid;
                if (TRANS_B) {
                    bf[g][0] = __float_as_uint(Bs[s][nc][kk + t4]);
                    bf[g][1] = __float_as_uint(Bs[s][nc][kk + 4 + t4]);
                } else {
                    bf[g][0] = __float_as_uint(Bs[s][kk + t4][nc]);
                    bf[g][1] = __float_as_uint(Bs[s][kk + 4 + t4][nc]);
                }
            }
            #pragma unroll
            for (int f = 0; f < 4; f++)
                #pragma unroll
                for (int g = 0; g < 4; g++)
                    mma_tf32(c[f][g], af[f], bf[g]);
        }

        if (kt + 1 < nt) { stsA(s ^ 1); stsB(s ^ 1); }
        __syncthreads();
    }

    // epilogue
    const float scale = 0.08838834764831845f;  // 1/sqrt(128)
    #pragma unroll
    for (int f = 0; f < 4; f++) {
        #pragma unroll
        for (int g = 0; g < 4; g++) {
            #pragma unroll
            for (int half = 0; half < 2; half++) {
                int m = m0 + wm + f * 16 + gid + half * 8;
                int n = n0 + wn + g * 8 + 2 * t4;
                float v0 = c[f][g][half * 2 + 0];
                float v1 = c[f][g][half * 2 + 1];
                size_t idx = (size_t)m * ldc + n;
                if (EPI == 0) {
                    C[idx] = v0; C[idx + 1] = v1;
                } else if (EPI == 1) {
                    C[idx]     = gelu_f(v0 + bias[n]);
                    C[idx + 1] = gelu_f(v1 + bias[n + 1]);
                } else if (EPI == 2) {
                    C[idx]     = C[idx]     + v0 + bias[n];
                    C[idx + 1] = C[idx + 1] + v1 + bias[n + 1];
                } else {
                    bool a0 = (n     <= m) && !((m >= BOTTLE) && (n     < BG));
                    bool a1 = (n + 1 <= m) && !((m >= BOTTLE) && (n + 1 < BG));
                    size_t bidx = (size_t)m * SEQ + n;
                    C[idx]     = v0 * scale + (a0 ? 0.f : -1e10f) + bias[bidx];
                    C[idx + 1] = v1 * scale + (a1 ? 0.f : -1e10f) + bias[bidx + 1];
                }
            }
        }
    }
}

// -------- row softmax over logits (in place), one block per (h, t) row --------
__global__ void softmax_kernel(float* __restrict__ logits) {
    size_t row = blockIdx.x;
    float* p = logits + row * SEQ;
    float mx = -INFINITY;
    for (int i = threadIdx.x; i < SEQ; i += blockDim.x) mx = fmaxf(mx, p[i]);
    mx = blockReduceMax(mx);
    float sum = 0.f;
    for (int i = threadIdx.x; i < SEQ; i += blockDim.x) {
        float e = __expf(p[i] - mx);
        p[i] = e;
        sum += e;
    }
    sum = blockReduceSum(sum);
    float inv = 1.0f / sum;
    for (int i = threadIdx.x; i < SEQ; i += blockDim.x) p[i] *= inv;
}

extern "C" void kernel_launch(void* const* d_in, const int* in_sizes, int n_in,
                              void* d_out, int out_size) {
    (void)in_sizes; (void)n_in; (void)out_size;
    const float* x         = (const float*)d_in[0];
    const float* attn_bias = (const float*)d_in[1];
    const float* ln_scale  = (const float*)d_in[2];
    const float* ln_offset = (const float*)d_in[3];
    const float* Wq = (const float*)d_in[4];
    const float* Wk = (const float*)d_in[5];
    const float* Wv = (const float*)d_in[6];
    const float* Wo = (const float*)d_in[7];
    const float* W1 = (const float*)d_in[8];
    const float* b1 = (const float*)d_in[9];
    const float* W2 = (const float*)d_in[10];
    const float* b2 = (const float*)d_in[11];
    float* out = (float*)d_out;

    float *xn, *q, *k, *v, *att, *ff, *logits;
    cudaGetSymbolAddress((void**)&xn,     g_xn);
    cudaGetSymbolAddress((void**)&q,      g_q);
    cudaGetSymbolAddress((void**)&k,      g_k);
    cudaGetSymbolAddress((void**)&v,      g_v);
    cudaGetSymbolAddress((void**)&att,    g_att);
    cudaGetSymbolAddress((void**)&ff,     g_ff);
    cudaGetSymbolAddress((void**)&logits, g_logits);

    // 1. LayerNorm
    ln_kernel<<<SEQ, 256>>>(x, ln_scale, ln_offset, xn);

    // 2. QKV projections (NN, tf32 tensor cores)
    dim3 g16(DMODEL / 128, SEQ / 128, 1);
    mma_gemm<0, 0><<<g16, 256>>>(xn, Wq, nullptr, q, SEQ, DMODEL, DMODEL,
                                 DMODEL, DMODEL, DMODEL, 0, 0, 0);
    mma_gemm<0, 0><<<g16, 256>>>(xn, Wk, nullptr, k, SEQ, DMODEL, DMODEL,
                                 DMODEL, DMODEL, DMODEL, 0, 0, 0);
    mma_gemm<0, 0><<<g16, 256>>>(xn, Wv, nullptr, v, SEQ, DMODEL, DMODEL,
                                 DMODEL, DMODEL, DMODEL, 0, 0, 0);

    // 3. RoPE
    rope_kernel<<<(SEQ * (DMODEL / 2) + 255) / 256, 256>>>(q, k);

    // 4. logits = q k^T / sqrt(dh) + mask + attn_bias   (NT, batched over heads)
    mma_gemm<1, 3><<<dim3(SEQ / 128, SEQ / 128, NH), 256>>>(
        q, k, attn_bias, logits, SEQ, SEQ, DH,
        DMODEL, DMODEL, SEQ, DH, DH, (size_t)SEQ * SEQ);

    // 5. softmax
    softmax_kernel<<<NH * SEQ, 256>>>(logits);

    // 6. attn_vec = weights @ v (NN, batched over heads)
    mma_gemm<0, 0><<<dim3(1, SEQ / 128, NH), 256>>>(
        logits, v, nullptr, att, SEQ, DH, SEQ,
        SEQ, DMODEL, DMODEL, (size_t)SEQ * SEQ, DH, DH);

    // 7. attn_out = attn_vec @ Wo  -> d_out
    mma_gemm<0, 0><<<g16, 256>>>(att, Wo, nullptr, out, SEQ, DMODEL, DMODEL,
                                 DMODEL, DMODEL, DMODEL, 0, 0, 0);

    // 8. ff = gelu(xn @ W1 + b1)
    mma_gemm<0, 1><<<dim3(DFF / 128, SEQ / 128, 1), 256>>>(
        xn, W1, b1, ff, SEQ, DFF, DMODEL, DMODEL, DFF, DFF, 0, 0, 0);

    // 9. out += ff @ W2 + b2
    mma_gemm<0, 2><<<g16, 256>>>(ff, W2, b2, out, SEQ, DMODEL, DFF,
                                 DFF, DMODEL, DMODEL, 0, 0, 0);
}

// round 4
// speedup vs baseline: 5.6138x; 1.7743x over previous
#include <cuda_runtime.h>
#include <math.h>
#include <stdint.h>

#define SEQ 2048
#define DMODEL 2048
#define NH 16
#define DH 128
#define DFF 8192
#define BOTTLE 1088   /* BACKGROUND_LEN + STYLE_VECS_LEN */
#define BG 1024       /* BACKGROUND_LEN */

// -------- scratch (no allocations allowed) --------
__device__ float g_xn[(size_t)SEQ * DMODEL];
__device__ float g_q[(size_t)SEQ * DMODEL];
__device__ float g_k[(size_t)SEQ * DMODEL];
__device__ float g_v[(size_t)SEQ * DMODEL];
__device__ float g_att[(size_t)SEQ * DMODEL];
__device__ float g_ff[(size_t)SEQ * DFF];
__device__ float g_logits[(size_t)NH * SEQ * SEQ];
// tf32-rounded weights
__device__ float g_wq[(size_t)DMODEL * DMODEL];
__device__ float g_wk[(size_t)DMODEL * DMODEL];
__device__ float g_wv[(size_t)DMODEL * DMODEL];
__device__ float g_wo[(size_t)DMODEL * DMODEL];
__device__ float g_w1[(size_t)DMODEL * DFF];
__device__ float g_w2[(size_t)DFF * DMODEL];

// -------- tf32 helpers --------
__device__ __forceinline__ uint32_t f2tf32(float f) {
    uint32_t u;
    asm("cvt.rna.tf32.f32 %0, %1;" : "=r"(u) : "f"(f));
    return u;
}
__device__ __forceinline__ float rnd_tf32(float f) { return __uint_as_float(f2tf32(f)); }
__device__ __forceinline__ float4 cvt4(float4 v) {
    float4 r;
    r.x = rnd_tf32(v.x); r.y = rnd_tf32(v.y); r.z = rnd_tf32(v.z); r.w = rnd_tf32(v.w);
    return r;
}
__device__ __forceinline__ void mma_tf32(float c[4], const uint32_t a[4], const uint32_t b[2]) {
    asm volatile(
        "mma.sync.aligned.m16n8k8.row.col.f32.tf32.tf32.f32 "
        "{%0,%1,%2,%3}, {%4,%5,%6,%7}, {%8,%9}, {%0,%1,%2,%3};\n"
        : "+f"(c[0]), "+f"(c[1]), "+f"(c[2]), "+f"(c[3])
        : "r"(a[0]), "r"(a[1]), "r"(a[2]), "r"(a[3]), "r"(b[0]), "r"(b[1]));
}

// -------- cp.async helpers --------
__device__ __forceinline__ void cp16(uint32_t s, const void* g) {
    asm volatile("cp.async.cg.shared.global [%0], [%1], 16;" :: "r"(s), "l"(g));
}
__device__ __forceinline__ void cp_commit() { asm volatile("cp.async.commit_group;"); }
template <int N> __device__ __forceinline__ void cp_wait() {
    asm volatile("cp.async.wait_group %0;" :: "n"(N));
}

// -------- reductions --------
__device__ __forceinline__ float blockReduceSum(float val) {
    __shared__ float sh[8];
    __shared__ float res;
    int lane = threadIdx.x & 31, w = threadIdx.x >> 5;
    #pragma unroll
    for (int o = 16; o > 0; o >>= 1) val += __shfl_xor_sync(0xffffffffu, val, o);
    if (lane == 0) sh[w] = val;
    __syncthreads();
    if (threadIdx.x == 0) {
        float s = 0.f;
        #pragma unroll
        for (int i = 0; i < 8; i++) s += sh[i];
        res = s;
    }
    __syncthreads();
    float r = res;
    __syncthreads();
    return r;
}

__device__ __forceinline__ float blockReduceMax(float val) {
    __shared__ float sh[8];
    __shared__ float res;
    int lane = threadIdx.x & 31, w = threadIdx.x >> 5;
    #pragma unroll
    for (int o = 16; o > 0; o >>= 1) val = fmaxf(val, __shfl_xor_sync(0xffffffffu, val, o));
    if (lane == 0) sh[w] = val;
    __syncthreads();
    if (threadIdx.x == 0) {
        float s = -INFINITY;
        #pragma unroll
        for (int i = 0; i < 8; i++) s = fmaxf(s, sh[i]);
        res = s;
    }
    __syncthreads();
    float r = res;
    __syncthreads();
    return r;
}

// -------- weight tf32 conversion --------
__global__ void cvt_tf32_kernel(const float4* __restrict__ in, float4* __restrict__ out, int n4) {
    int i = blockIdx.x * blockDim.x + threadIdx.x;
    if (i < n4) out[i] = cvt4(in[i]);
}

// -------- LayerNorm (output rounded to tf32: it only feeds GEMMs) --------
__global__ void ln_kernel(const float* __restrict__ x, const float* __restrict__ sc,
                          const float* __restrict__ of, float* __restrict__ out) {
    int row = blockIdx.x;
    const float* xr = x + (size_t)row * DMODEL;
    float* o = out + (size_t)row * DMODEL;
    float s = 0.f, s2 = 0.f;
    for (int i = threadIdx.x; i < DMODEL; i += blockDim.x) {
        float v = xr[i];
        s += v; s2 += v * v;
    }
    s  = blockReduceSum(s);
    s2 = blockReduceSum(s2);
    float mean = s / DMODEL;
    float var  = s2 / DMODEL - mean * mean;
    float r = rsqrtf(var + 1e-5f);
    for (int i = threadIdx.x; i < DMODEL; i += blockDim.x)
        o[i] = rnd_tf32(sc[i] * r * (xr[i] - mean) + of[i]);
}

// -------- RoPE (in place; rounds q,k to tf32 for QK^T gemm) --------
__global__ void rope_kernel(float* __restrict__ q, float* __restrict__ k) {
    int idx = blockIdx.x * blockDim.x + threadIdx.x;
    if (idx >= SEQ * (DMODEL / 2)) return;
    int t = idx / (DMODEL / 2);
    int r = idx % (DMODEL / 2);
    int h = r / (DH / 2);
    int i = r % (DH / 2);
    float inv = powf(10000.0f, -(float)(2 * i) / (float)DH);
    float ang = (float)t * inv;
    float s, c;
    sincosf(ang, &s, &c);
    size_t base = (size_t)t * DMODEL + (size_t)h * DH + 2 * i;
    float q0 = q[base], q1 = q[base + 1];
    q[base]     = rnd_tf32(q0 * c - q1 * s);
    q[base + 1] = rnd_tf32(q1 * c + q0 * s);
    float k0 = k[base], k1 = k[base + 1];
    k[base]     = rnd_tf32(k0 * c - k1 * s);
    k[base + 1] = rnd_tf32(k1 * c + k0 * s);
}

// -------- GELU (tanh approx == jax.nn.gelu default) --------
__device__ __forceinline__ float gelu_f(float x) {
    float x3 = x * x * x;
    return 0.5f * x * (1.0f + tanhf(0.7978845608028654f * (x + 0.044715f * x3)));
}

// ============ TF32 tensor-core GEMM, cp.async 4-stage pipeline ============
// C[M,N] = A[M,K] @ op(B). TRANS_B=0: B[K,N]. TRANS_B=1: B[N,K]^T.
// Operands must already be tf32-rounded.
// EPI 0: C = acc
// EPI 1: C = gelu(acc + bias[n])
// EPI 2: C = C + acc + bias[n]
// EPI 3: C = acc/sqrt(DH) + causal/bottleneck mask + bias[m*SEQ+n]
// ROUND: round stored value to tf32 (when C feeds another GEMM).
template <int TRANS_B, int EPI, int ROUND>
__global__ __launch_bounds__(256, 2)
void mma_gemm(const float* __restrict__ A, const float* __restrict__ B,
              const float* __restrict__ bias, float* __restrict__ C,
              int M, int N, int K, int lda, int ldb, int ldc,
              size_t sA, size_t sB, size_t sC) {
    constexpr int S = 4, BK = 16;
    constexpr int ASTR = 20;
    constexpr int BROWS = TRANS_B ? 128 : 16;
    constexpr int BSTR  = TRANS_B ? 20  : 136;
    constexpr int ASTAGE = 128 * ASTR;   // floats per stage
    constexpr int BSTAGE = BROWS * BSTR;

    extern __shared__ float smdyn[];
    float* Asm = smdyn;
    float* Bsm = smdyn + S * ASTAGE;

    int z = blockIdx.z;
    A += (size_t)z * sA;
    B += (size_t)z * sB;
    C += (size_t)z * sC;

    int t = threadIdx.x;
    int m0 = blockIdx.y * 128, n0 = blockIdx.x * 128;
    int lane = t & 31, warp = t >> 5;
    int wm = (warp >> 2) * 64;    // 0 or 64
    int wn = (warp & 3) * 32;     // 0,32,64,96
    int gid = lane >> 2, t4 = lane & 3;

    float acc[4][4][4];
    #pragma unroll
    for (int f = 0; f < 4; f++)
        #pragma unroll
        for (int g = 0; g < 4; g++)
            #pragma unroll
            for (int e = 0; e < 4; e++) acc[f][g][e] = 0.f;

    // loader indexing
    int aRow = t >> 2, aK = (t & 3) * 4;
    const float* Ap = A + (size_t)(m0 + aRow) * lda + aK;
    uint32_t aSm = (uint32_t)__cvta_generic_to_shared(Asm) + (uint32_t)((aRow * ASTR + aK) * 4);

    const float* Bp;
    uint32_t bSm;
    int bK = t >> 5, bN = (t & 31) * 4;
    if (TRANS_B) {
        Bp  = B + (size_t)(n0 + aRow) * ldb + aK;
        bSm = (uint32_t)__cvta_generic_to_shared(Bsm) + (uint32_t)((aRow * BSTR + aK) * 4);
    } else {
        Bp  = B + (size_t)bK * ldb + n0 + bN;
        bSm = (uint32_t)__cvta_generic_to_shared(Bsm) + (uint32_t)((bK * BSTR + bN) * 4);
    }

    int nt = K / BK;

    auto load_stage = [&](int s, int tile) {
        int k0 = tile * BK;
        cp16(aSm + s * ASTAGE * 4, Ap + k0);
        cp16(aSm + s * ASTAGE * 4 + 64 * ASTR * 4, Ap + (size_t)64 * lda + k0);
        if (TRANS_B) {
            cp16(bSm + s * BSTAGE * 4, Bp + k0);
            cp16(bSm + s * BSTAGE * 4 + 64 * BSTR * 4, Bp + (size_t)64 * ldb + k0);
        } else {
            cp16(bSm + s * BSTAGE * 4, Bp + (size_t)k0 * ldb);
            cp16(bSm + s * BSTAGE * 4 + 8 * BSTR * 4, Bp + (size_t)(k0 + 8) * ldb);
        }
    };

    #pragma unroll
    for (int s = 0; s < S - 1; s++) {
        if (s < nt) load_stage(s, s);
        cp_commit();
    }

    for (int kt = 0; kt < nt; kt++) {
        cp_wait<S - 2>();
        __syncthreads();
        int nx = kt + S - 1;
        if (nx < nt) load_stage(nx & (S - 1), nx);
        cp_commit();

        const float* As_ = Asm + (kt & (S - 1)) * ASTAGE;
        const float* Bs_ = Bsm + (kt & (S - 1)) * BSTAGE;
        #pragma unroll
        for (int kk = 0; kk < BK; kk += 8) {
            uint32_t af[4][4];
            #pragma unroll
            for (int f = 0; f < 4; f++) {
                int mr = wm + f * 16 + gid;
                af[f][0] = __float_as_uint(As_[mr * ASTR + kk + t4]);
                af[f][1] = __float_as_uint(As_[(mr + 8) * ASTR + kk + t4]);
                af[f][2] = __float_as_uint(As_[mr * ASTR + kk + 4 + t4]);
                af[f][3] = __float_as_uint(As_[(mr + 8) * ASTR + kk + 4 + t4]);
            }
            uint32_t bf[4][2];
            #pragma unroll
            for (int g = 0; g < 4; g++) {
                int nc = wn + g * 8 + gid;
                if (TRANS_B) {
                    bf[g][0] = __float_as_uint(Bs_[nc * BSTR + kk + t4]);
                    bf[g][1] = __float_as_uint(Bs_[nc * BSTR + kk + 4 + t4]);
                } else {
                    bf[g][0] = __float_as_uint(Bs_[(kk + t4) * BSTR + nc]);
                    bf[g][1] = __float_as_uint(Bs_[(kk + 4 + t4) * BSTR + nc]);
                }
            }
            #pragma unroll
            for (int f = 0; f < 4; f++)
                #pragma unroll
                for (int g = 0; g < 4; g++)
                    mma_tf32(acc[f][g], af[f], bf[g]);
        }
    }

    // epilogue
    const float scale = 0.08838834764831845f;  // 1/sqrt(128)
    #pragma unroll
    for (int f = 0; f < 4; f++) {
        #pragma unroll
        for (int g = 0; g < 4; g++) {
            #pragma unroll
            for (int half = 0; half < 2; half++) {
                int m = m0 + wm + f * 16 + gid + half * 8;
                int n = n0 + wn + g * 8 + 2 * t4;
                float v0 = acc[f][g][half * 2 + 0];
                float v1 = acc[f][g][half * 2 + 1];
                size_t idx = (size_t)m * ldc + n;
                if (EPI == 1) {
                    v0 = gelu_f(v0 + bias[n]);
                    v1 = gelu_f(v1 + bias[n + 1]);
                } else if (EPI == 2) {
                    v0 = C[idx]     + v0 + bias[n];
                    v1 = C[idx + 1] + v1 + bias[n + 1];
                } else if (EPI == 3) {
                    bool a0 = (n     <= m) && !((m >= BOTTLE) && (n     < BG));
                    bool a1 = (n + 1 <= m) && !((m >= BOTTLE) && (n + 1 < BG));
                    size_t bidx = (size_t)m * SEQ + n;
                    v0 = v0 * scale + (a0 ? 0.f : -1e10f) + bias[bidx];
                    v1 = v1 * scale + (a1 ? 0.f : -1e10f) + bias[bidx + 1];
                }
                if (ROUND) { v0 = rnd_tf32(v0); v1 = rnd_tf32(v1); }
                C[idx]     = v0;
                C[idx + 1] = v1;
            }
        }
    }
}

// -------- row softmax (in place); probs rounded to tf32 for AV gemm --------
__global__ void softmax_kernel(float* __restrict__ logits) {
    size_t row = blockIdx.x;
    float* p = logits + row * SEQ;
    float mx = -INFINITY;
    for (int i = threadIdx.x; i < SEQ; i += blockDim.x) mx = fmaxf(mx, p[i]);
    mx = blockReduceMax(mx);
    float sum = 0.f;
    for (int i = threadIdx.x; i < SEQ; i += blockDim.x) {
        float e = __expf(p[i] - mx);
        p[i] = e;
        sum += e;
    }
    sum = blockReduceSum(sum);
    float inv = 1.0f / sum;
    for (int i = threadIdx.x; i < SEQ; i += blockDim.x) p[i] = rnd_tf32(p[i] * inv);
}

extern "C" void kernel_launch(void* const* d_in, const int* in_sizes, int n_in,
                              void* d_out, int out_size) {
    (void)in_sizes; (void)n_in; (void)out_size;
    const float* x         = (const float*)d_in[0];
    const float* attn_bias = (const float*)d_in[1];
    const float* ln_scale  = (const float*)d_in[2];
    const float* ln_offset = (const float*)d_in[3];
    const float* Wq = (const float*)d_in[4];
    const float* Wk = (const float*)d_in[5];
    const float* Wv = (const float*)d_in[6];
    const float* Wo = (const float*)d_in[7];
    const float* W1 = (const float*)d_in[8];
    const float* b1 = (const float*)d_in[9];
    const float* W2 = (const float*)d_in[10];
    const float* b2 = (const float*)d_in[11];
    float* out = (float*)d_out;

    float *xn, *q, *k, *v, *att, *ff, *logits;
    float *wq, *wk, *wv, *wo, *w1, *w2;
    cudaGetSymbolAddress((void**)&xn,     g_xn);
    cudaGetSymbolAddress((void**)&q,      g_q);
    cudaGetSymbolAddress((void**)&k,      g_k);
    cudaGetSymbolAddress((void**)&v,      g_v);
    cudaGetSymbolAddress((void**)&att,    g_att);
    cudaGetSymbolAddress((void**)&ff,     g_ff);
    cudaGetSymbolAddress((void**)&logits, g_logits);
    cudaGetSymbolAddress((void**)&wq, g_wq);
    cudaGetSymbolAddress((void**)&wk, g_wk);
    cudaGetSymbolAddress((void**)&wv, g_wv);
    cudaGetSymbolAddress((void**)&wo, g_wo);
    cudaGetSymbolAddress((void**)&w1, g_w1);
    cudaGetSymbolAddress((void**)&w2, g_w2);

    // smem sizes per instantiation
    const int SM_NN = (4 * 128 * 20 + 4 * 16 * 136) * 4;   // 75776
    const int SM_T  = (4 * 128 * 20 + 4 * 128 * 20) * 4;   // 81920
    cudaFuncSetAttribute(mma_gemm<0, 0, 0>, cudaFuncAttributeMaxDynamicSharedMemorySize, SM_NN);
    cudaFuncSetAttribute(mma_gemm<0, 0, 1>, cudaFuncAttributeMaxDynamicSharedMemorySize, SM_NN);
    cudaFuncSetAttribute(mma_gemm<0, 1, 1>, cudaFuncAttributeMaxDynamicSharedMemorySize, SM_NN);
    cudaFuncSetAttribute(mma_gemm<0, 2, 0>, cudaFuncAttributeMaxDynamicSharedMemorySize, SM_NN);
    cudaFuncSetAttribute(mma_gemm<1, 3, 0>, cudaFuncAttributeMaxDynamicSharedMemorySize, SM_T);

    // 0. Round weights to tf32 once per launch
    {
        int thr = 256;
        int n4a = DMODEL * DMODEL / 4;
        int n4b = DMODEL * DFF / 4;
        cvt_tf32_kernel<<<(n4a + thr - 1) / thr, thr>>>((const float4*)Wq, (float4*)wq, n4a);
        cvt_tf32_kernel<<<(n4a + thr - 1) / thr, thr>>>((const float4*)Wk, (float4*)wk, n4a);
        cvt_tf32_kernel<<<(n4a + thr - 1) / thr, thr>>>((const float4*)Wv, (float4*)wv, n4a);
        cvt_tf32_kernel<<<(n4a + thr - 1) / thr, thr>>>((const float4*)Wo, (float4*)wo, n4a);
        cvt_tf32_kernel<<<(n4b + thr - 1) / thr, thr>>>((const float4*)W1, (float4*)w1, n4b);
        cvt_tf32_kernel<<<(n4b + thr - 1) / thr, thr>>>((const float4*)W2, (float4*)w2, n4b);
    }

    // 1. LayerNorm (tf32-rounded output)
    ln_kernel<<<SEQ, 256>>>(x, ln_scale, ln_offset, xn);

    // 2. QKV projections
    dim3 g16(DMODEL / 128, SEQ / 128, 1);
    mma_gemm<0, 0, 0><<<g16, 256, SM_NN>>>(xn, wq, nullptr, q, SEQ, DMODEL, DMODEL,
                                           DMODEL, DMODEL, DMODEL, 0, 0, 0);
    mma_gemm<0, 0, 0><<<g16, 256, SM_NN>>>(xn, wk, nullptr, k, SEQ, DMODEL, DMODEL,
                                           DMODEL, DMODEL, DMODEL, 0, 0, 0);
    mma_gemm<0, 0, 1><<<g16, 256, SM_NN>>>(xn, wv, nullptr, v, SEQ, DMODEL, DMODEL,
                                           DMODEL, DMODEL, DMODEL, 0, 0, 0);

    // 3. RoPE (rounds q,k)
    rope_kernel<<<(SEQ * (DMODEL / 2) + 255) / 256, 256>>>(q, k);

    // 4. logits = q k^T / sqrt(dh) + mask + attn_bias   (NT, batched over heads)
    mma_gemm<1, 3, 0><<<dim3(SEQ / 128, SEQ / 128, NH), 256, SM_T>>>(
        q, k, attn_bias, logits, SEQ, SEQ, DH,
        DMODEL, DMODEL, SEQ, DH, DH, (size_t)SEQ * SEQ);

    // 5. softmax (rounds probs)
    softmax_kernel<<<NH * SEQ, 256>>>(logits);

    // 6. attn_vec = weights @ v (NN, batched over heads, rounded)
    mma_gemm<0, 0, 1><<<dim3(1, SEQ / 128, NH), 256, SM_NN>>>(
        logits, v, nullptr, att, SEQ, DH, SEQ,
        SEQ, DMODEL, DMODEL, (size_t)SEQ * SEQ, DH, DH);

    // 7. attn_out = attn_vec @ Wo -> d_out
    mma_gemm<0, 0, 0><<<g16, 256, SM_NN>>>(att, wo, nullptr, out, SEQ, DMODEL, DMODEL,
                                           DMODEL, DMODEL, DMODEL, 0, 0, 0);

    // 8. ff = gelu(xn @ W1 + b1)   (rounded)
    mma_gemm<0, 1, 1><<<dim3(DFF / 128, SEQ / 128, 1), 256, SM_NN>>>(
        xn, w1, b1, ff, SEQ, DFF, DMODEL, DMODEL, DFF, DFF, 0, 0, 0);

    // 9. out += ff @ W2 + b2
    mma_gemm<0, 2, 0><<<g16, 256, SM_NN>>>(ff, w2, b2, out, SEQ, DMODEL, DFF,
                                           DFF, DMODEL, DMODEL, 0, 0, 0);
}

// round 5
// speedup vs baseline: 6.5902x; 1.1739x over previous
#include <cuda_runtime.h>
#include <math.h>
#include <stdint.h>

#define SEQ 2048
#define DMODEL 2048
#define NH 16
#define DH 128
#define DFF 8192
#define BOTTLE 1088   /* BACKGROUND_LEN + STYLE_VECS_LEN */
#define BG 1024       /* BACKGROUND_LEN */

// -------- scratch (no allocations allowed) --------
__device__ float g_xn[(size_t)SEQ * DMODEL];
__device__ float g_qkv[(size_t)SEQ * 3 * DMODEL];
__device__ float g_att[(size_t)SEQ * DMODEL];
__device__ float g_ff[(size_t)SEQ * DFF];
// tf32-rounded weights
__device__ float g_wqkv[(size_t)DMODEL * 3 * DMODEL];
__device__ float g_wo[(size_t)DMODEL * DMODEL];
__device__ float g_w1[(size_t)DMODEL * DFF];
__device__ float g_w2[(size_t)DFF * DMODEL];

// -------- tf32 helpers --------
__device__ __forceinline__ uint32_t f2tf32(float f) {
    uint32_t u;
    asm("cvt.rna.tf32.f32 %0, %1;" : "=r"(u) : "f"(f));
    return u;
}
__device__ __forceinline__ float rnd_tf32(float f) { return __uint_as_float(f2tf32(f)); }
__device__ __forceinline__ float4 cvt4(float4 v) {
    float4 r;
    r.x = rnd_tf32(v.x); r.y = rnd_tf32(v.y); r.z = rnd_tf32(v.z); r.w = rnd_tf32(v.w);
    return r;
}
__device__ __forceinline__ void mma_tf32(float c[4], const uint32_t a[4], const uint32_t b[2]) {
    asm volatile(
        "mma.sync.aligned.m16n8k8.row.col.f32.tf32.tf32.f32 "
        "{%0,%1,%2,%3}, {%4,%5,%6,%7}, {%8,%9}, {%0,%1,%2,%3};\n"
        : "+f"(c[0]), "+f"(c[1]), "+f"(c[2]), "+f"(c[3])
        : "r"(a[0]), "r"(a[1]), "r"(a[2]), "r"(a[3]), "r"(b[0]), "r"(b[1]));
}

// -------- cp.async helpers --------
__device__ __forceinline__ void cp16(uint32_t s, const void* g) {
    asm volatile("cp.async.cg.shared.global [%0], [%1], 16;" :: "r"(s), "l"(g));
}
__device__ __forceinline__ void cp_commit() { asm volatile("cp.async.commit_group;"); }
template <int N> __device__ __forceinline__ void cp_wait() {
    asm volatile("cp.async.wait_group %0;" :: "n"(N));
}

// -------- reductions --------
__device__ __forceinline__ float blockReduceSum(float val) {
    __shared__ float sh[8];
    __shared__ float res;
    int lane = threadIdx.x & 31, w = threadIdx.x >> 5;
    #pragma unroll
    for (int o = 16; o > 0; o >>= 1) val += __shfl_xor_sync(0xffffffffu, val, o);
    if (lane == 0) sh[w] = val;
    __syncthreads();
    if (threadIdx.x == 0) {
        float s = 0.f;
        #pragma unroll
        for (int i = 0; i < 8; i++) s += sh[i];
        res = s;
    }
    __syncthreads();
    float r = res;
    __syncthreads();
    return r;
}

// -------- weight tf32 conversion --------
__global__ void cvt_tf32_kernel(const float4* __restrict__ in, float4* __restrict__ out, int n4) {
    int i = blockIdx.x * blockDim.x + threadIdx.x;
    if (i < n4) out[i] = cvt4(in[i]);
}

// pack Wq|Wk|Wv -> [2048][6144] tf32
__global__ void cvt_pack3_kernel(const float4* __restrict__ a, const float4* __restrict__ b,
                                 const float4* __restrict__ c, float4* __restrict__ out) {
    int i = blockIdx.x * blockDim.x + threadIdx.x;  // over 2048 * 512 * 3
    if (i >= DMODEL * (DMODEL / 4) * 3) return;
    int row = i / (3 * DMODEL / 4);
    int rem = i % (3 * DMODEL / 4);
    int sel = rem / (DMODEL / 4);
    int col = rem % (DMODEL / 4);
    const float4* src = (sel == 0) ? a : (sel == 1) ? b : c;
    out[(size_t)row * (3 * DMODEL / 4) + sel * (DMODEL / 4) + col] =
        cvt4(src[(size_t)row * (DMODEL / 4) + col]);
}

// -------- LayerNorm (tf32-rounded output; it only feeds GEMMs) --------
__global__ void ln_kernel(const float* __restrict__ x, const float* __restrict__ sc,
                          const float* __restrict__ of, float* __restrict__ out) {
    int row = blockIdx.x;
    const float* xr = x + (size_t)row * DMODEL;
    float* o = out + (size_t)row * DMODEL;
    float s = 0.f, s2 = 0.f;
    for (int i = threadIdx.x; i < DMODEL; i += blockDim.x) {
        float v = xr[i];
        s += v; s2 += v * v;
    }
    s  = blockReduceSum(s);
    s2 = blockReduceSum(s2);
    float mean = s / DMODEL;
    float var  = s2 / DMODEL - mean * mean;
    float r = rsqrtf(var + 1e-5f);
    for (int i = threadIdx.x; i < DMODEL; i += blockDim.x)
        o[i] = rnd_tf32(sc[i] * r * (xr[i] - mean) + of[i]);
}

// -------- RoPE on packed qkv (q at col 0, k at col DMODEL), tf32-rounded --------
__global__ void rope_kernel(float* __restrict__ qkv) {
    int idx = blockIdx.x * blockDim.x + threadIdx.x;
    if (idx >= SEQ * (DMODEL / 2)) return;
    int t = idx / (DMODEL / 2);
    int r = idx % (DMODEL / 2);
    int h = r / (DH / 2);
    int i = r % (DH / 2);
    float inv = powf(10000.0f, -(float)(2 * i) / (float)DH);
    float ang = (float)t * inv;
    float s, c;
    sincosf(ang, &s, &c);
    size_t base = (size_t)t * (3 * DMODEL) + (size_t)h * DH + 2 * i;
    float q0 = qkv[base], q1 = qkv[base + 1];
    qkv[base]     = rnd_tf32(q0 * c - q1 * s);
    qkv[base + 1] = rnd_tf32(q1 * c + q0 * s);
    size_t kb = base + DMODEL;
    float k0 = qkv[kb], k1 = qkv[kb + 1];
    qkv[kb]     = rnd_tf32(k0 * c - k1 * s);
    qkv[kb + 1] = rnd_tf32(k1 * c + k0 * s);
}

// -------- GELU (tanh approx == jax.nn.gelu default) --------
__device__ __forceinline__ float gelu_f(float x) {
    float x3 = x * x * x;
    return 0.5f * x * (1.0f + tanhf(0.7978845608028654f * (x + 0.044715f * x3)));
}

// ============ TF32 tensor-core GEMM, cp.async 4-stage pipeline (NN only) ============
// EPI 0: C = acc     EPI 1: C = gelu(acc + bias[n])     EPI 2: C = C + acc + bias[n]
// ROUND: round stored value to tf32.
template <int EPI, int ROUND>
__global__ __launch_bounds__(256, 2)
void mma_gemm(const float* __restrict__ A, const float* __restrict__ B,
              const float* __restrict__ bias, float* __restrict__ C,
              int M, int N, int K, int lda, int ldb, int ldc) {
    constexpr int S = 4, BK = 16;
    constexpr int ASTR = 20, BSTR = 136;
    constexpr int ASTAGE = 128 * ASTR;
    constexpr int BSTAGE = 16 * BSTR;

    extern __shared__ float smdyn[];
    float* Asm = smdyn;
    float* Bsm = smdyn + S * ASTAGE;

    int t = threadIdx.x;
    int m0 = blockIdx.y * 128, n0 = blockIdx.x * 128;
    int lane = t & 31, warp = t >> 5;
    int wm = (warp >> 2) * 64;
    int wn = (warp & 3) * 32;
    int gid = lane >> 2, t4 = lane & 3;

    float acc[4][4][4];
    #pragma unroll
    for (int f = 0; f < 4; f++)
        #pragma unroll
        for (int g = 0; g < 4; g++)
            #pragma unroll
            for (int e = 0; e < 4; e++) acc[f][g][e] = 0.f;

    int aRow = t >> 2, aK = (t & 3) * 4;
    const float* Ap = A + (size_t)(m0 + aRow) * lda + aK;
    uint32_t aSm = (uint32_t)__cvta_generic_to_shared(Asm) + (uint32_t)((aRow * ASTR + aK) * 4);

    int bK = t >> 5, bN = (t & 31) * 4;
    const float* Bp = B + (size_t)bK * ldb + n0 + bN;
    uint32_t bSm = (uint32_t)__cvta_generic_to_shared(Bsm) + (uint32_t)((bK * BSTR + bN) * 4);

    int nt = K / BK;

    auto load_stage = [&](int s, int tile) {
        int k0 = tile * BK;
        cp16(aSm + s * ASTAGE * 4, Ap + k0);
        cp16(aSm + s * ASTAGE * 4 + 64 * ASTR * 4, Ap + (size_t)64 * lda + k0);
        cp16(bSm + s * BSTAGE * 4, Bp + (size_t)k0 * ldb);
        cp16(bSm + s * BSTAGE * 4 + 8 * BSTR * 4, Bp + (size_t)(k0 + 8) * ldb);
    };

    #pragma unroll
    for (int s = 0; s < S - 1; s++) {
        if (s < nt) load_stage(s, s);
        cp_commit();
    }

    for (int kt = 0; kt < nt; kt++) {
        cp_wait<S - 2>();
        __syncthreads();
        int nx = kt + S - 1;
        if (nx < nt) load_stage(nx & (S - 1), nx);
        cp_commit();

        const float* As_ = Asm + (kt & (S - 1)) * ASTAGE;
        const float* Bs_ = Bsm + (kt & (S - 1)) * BSTAGE;
        #pragma unroll
        for (int kk = 0; kk < BK; kk += 8) {
            uint32_t af[4][4];
            #pragma unroll
            for (int f = 0; f < 4; f++) {
                int mr = wm + f * 16 + gid;
                af[f][0] = __float_as_uint(As_[mr * ASTR + kk + t4]);
                af[f][1] = __float_as_uint(As_[(mr + 8) * ASTR + kk + t4]);
                af[f][2] = __float_as_uint(As_[mr * ASTR + kk + 4 + t4]);
                af[f][3] = __float_as_uint(As_[(mr + 8) * ASTR + kk + 4 + t4]);
            }
            uint32_t bf[4][2];
            #pragma unroll
            for (int g = 0; g < 4; g++) {
                int nc = wn + g * 8 + gid;
                bf[g][0] = __float_as_uint(Bs_[(kk + t4) * BSTR + nc]);
                bf[g][1] = __float_as_uint(Bs_[(kk + 4 + t4) * BSTR + nc]);
            }
            #pragma unroll
            for (int f = 0; f < 4; f++)
                #pragma unroll
                for (int g = 0; g < 4; g++)
                    mma_tf32(acc[f][g], af[f], bf[g]);
        }
    }

    #pragma unroll
    for (int f = 0; f < 4; f++) {
        #pragma unroll
        for (int g = 0; g < 4; g++) {
            #pragma unroll
            for (int half = 0; half < 2; half++) {
                int m = m0 + wm + f * 16 + gid + half * 8;
                int n = n0 + wn + g * 8 + 2 * t4;
                float v0 = acc[f][g][half * 2 + 0];
                float v1 = acc[f][g][half * 2 + 1];
                size_t idx = (size_t)m * ldc + n;
                if (EPI == 1) {
                    v0 = gelu_f(v0 + bias[n]);
                    v1 = gelu_f(v1 + bias[n + 1]);
                } else if (EPI == 2) {
                    v0 = C[idx]     + v0 + bias[n];
                    v1 = C[idx + 1] + v1 + bias[n + 1];
                }
                if (ROUND) { v0 = rnd_tf32(v0); v1 = rnd_tf32(v1); }
                C[idx]     = v0;
                C[idx + 1] = v1;
            }
        }
    }
}

// ============ Flash attention (tf32 mma, online softmax) ============
// 256 threads = 8 warps, each warp owns 16 rows x full 128-col tile.
// smem: Qs + Ks + Vs, each 128x132 fp32 (203 KB total), single-buffered with
// cp.async overlap (V loads under QK^T, next K loads under softmax+PV).
__global__ void __launch_bounds__(256, 1)
flash_kernel(const float* __restrict__ qkv, const float* __restrict__ bias,
             float* __restrict__ att) {
    constexpr int LD = 3 * DMODEL;
    constexpr int STR = 132;
    extern __shared__ float sm[];
    float* Qs = sm;
    float* Ks = sm + 128 * STR;
    float* Vs = sm + 2 * 128 * STR;

    int mb = blockIdx.x, h = blockIdx.y;
    int m0 = mb * 128;
    int t = threadIdx.x, lane = t & 31, warp = t >> 5;
    int gid = lane >> 2, t4 = lane & 3;
    int wrow = warp * 16;

    const float* kbase = qkv + DMODEL + h * DH;
    const float* vbase = qkv + 2 * DMODEL + h * DH;

    int lr = t >> 1, lc = (t & 1) * 64;

    // Q load + first K tile
    int it0 = (m0 >= 1152) ? 8 : 0;
    {
        const float* g = qkv + (size_t)(m0 + lr) * LD + h * DH + lc;
        uint32_t s = (uint32_t)__cvta_generic_to_shared(Qs + lr * STR + lc);
        #pragma unroll
        for (int i = 0; i < 16; i++) cp16(s + i * 16, g + i * 4);
    }
    {
        const float* g = kbase + (size_t)(it0 * 128 + lr) * LD + lc;
        uint32_t s = (uint32_t)__cvta_generic_to_shared(Ks + lr * STR + lc);
        #pragma unroll
        for (int i = 0; i < 16; i++) cp16(s + i * 16, g + i * 4);
    }
    cp_commit();
    cp_wait<0>();
    __syncthreads();

    float o[16][4];
    #pragma unroll
    for (int g = 0; g < 16; g++) { o[g][0] = o[g][1] = o[g][2] = o[g][3] = 0.f; }
    float mrow0 = -INFINITY, mrow1 = -INFINITY;
    float lsum0 = 0.f, lsum1 = 0.f;

    const float scale = 0.08838834764831845f;  // 1/sqrt(128)
    int me0 = m0 + wrow + gid;
    int me1 = me0 + 8;

    for (int it = it0; it <= mb; it++) {
        int n0 = it * 128;

        // prefetch V_it (needed only after softmax)
        {
            const float* g = vbase + (size_t)(n0 + lr) * LD + lc;
            uint32_t s = (uint32_t)__cvta_generic_to_shared(Vs + lr * STR + lc);
            #pragma unroll
            for (int i = 0; i < 16; i++) cp16(s + i * 16, g + i * 4);
            cp_commit();
        }

        // S = Q K^T
        float s[16][4];
        #pragma unroll
        for (int g = 0; g < 16; g++) s[g][0] = s[g][1] = s[g][2] = s[g][3] = 0.f;

        #pragma unroll
        for (int kt = 0; kt < 16; kt++) {
            uint32_t a[4];
            int kc = kt * 8;
            a[0] = __float_as_uint(Qs[(wrow + gid)     * STR + kc + t4]);
            a[1] = __float_as_uint(Qs[(wrow + gid + 8) * STR + kc + t4]);
            a[2] = __float_as_uint(Qs[(wrow + gid)     * STR + kc + 4 + t4]);
            a[3] = __float_as_uint(Qs[(wrow + gid + 8) * STR + kc + 4 + t4]);
            #pragma unroll
            for (int g = 0; g < 16; g++) {
                uint32_t b[2];
                b[0] = __float_as_uint(Ks[(g * 8 + gid) * STR + kc + t4]);
                b[1] = __float_as_uint(Ks[(g * 8 + gid) * STR + kc + 4 + t4]);
                mma_tf32(s[g], a, b);
            }
        }
        __syncthreads();   // all warps done reading Ks

        // prefetch K_{it+1} into Ks
        if (it < mb) {
            const float* g = kbase + (size_t)(n0 + 128 + lr) * LD + lc;
            uint32_t sa = (uint32_t)__cvta_generic_to_shared(Ks + lr * STR + lc);
            #pragma unroll
            for (int i = 0; i < 16; i++) cp16(sa + i * 16, g + i * 4);
        }
        cp_commit();

        // ---- online softmax (registers only) ----
        float mx0 = -INFINITY, mx1 = -INFINITY;
        const float* bp0 = bias + (size_t)me0 * SEQ + n0 + 2 * t4;
        const float* bp1 = bias + (size_t)me1 * SEQ + n0 + 2 * t4;
        #pragma unroll
        for (int g = 0; g < 16; g++) {
            int nc = n0 + g * 8 + 2 * t4;
            float2 b0 = *(const float2*)(bp0 + g * 8);
            float2 b1 = *(const float2*)(bp1 + g * 8);
            bool a00 = (nc     <= me0) && !((me0 >= BOTTLE) && (nc     < BG));
            bool a01 = (nc + 1 <= me0) && !((me0 >= BOTTLE) && (nc + 1 < BG));
            bool a10 = (nc     <= me1) && !((me1 >= BOTTLE) && (nc     < BG));
            bool a11 = (nc + 1 <= me1) && !((me1 >= BOTTLE) && (nc + 1 < BG));
            s[g][0] = s[g][0] * scale + (a00 ? 0.f : -1e10f) + b0.x;
            s[g][1] = s[g][1] * scale + (a01 ? 0.f : -1e10f) + b0.y;
            s[g][2] = s[g][2] * scale + (a10 ? 0.f : -1e10f) + b1.x;
            s[g][3] = s[g][3] * scale + (a11 ? 0.f : -1e10f) + b1.y;
            mx0 = fmaxf(mx0, fmaxf(s[g][0], s[g][1]));
            mx1 = fmaxf(mx1, fmaxf(s[g][2], s[g][3]));
        }
        mx0 = fmaxf(mx0, __shfl_xor_sync(0xffffffffu, mx0, 1));
        mx0 = fmaxf(mx0, __shfl_xor_sync(0xffffffffu, mx0, 2));
        mx1 = fmaxf(mx1, __shfl_xor_sync(0xffffffffu, mx1, 1));
        mx1 = fmaxf(mx1, __shfl_xor_sync(0xffffffffu, mx1, 2));
        float mn0 = fmaxf(mrow0, mx0), mn1 = fmaxf(mrow1, mx1);
        float al0 = __expf(mrow0 - mn0), al1 = __expf(mrow1 - mn1);
        float rs0 = 0.f, rs1 = 0.f;
        #pragma unroll
        for (int g = 0; g < 16; g++) {
            float p0 = __expf(s[g][0] - mn0), p1 = __expf(s[g][1] - mn0);
            float p2 = __expf(s[g][2] - mn1), p3 = __expf(s[g][3] - mn1);
            rs0 += p0 + p1; rs1 += p2 + p3;
            s[g][0] = rnd_tf32(p0); s[g][1] = rnd_tf32(p1);
            s[g][2] = rnd_tf32(p2); s[g][3] = rnd_tf32(p3);
        }
        lsum0 = lsum0 * al0 + rs0;
        lsum1 = lsum1 * al1 + rs1;
        mrow0 = mn0; mrow1 = mn1;
        #pragma unroll
        for (int g = 0; g < 16; g++) {
            o[g][0] *= al0; o[g][1] *= al0; o[g][2] *= al1; o[g][3] *= al1;
        }

        cp_wait<1>();      // V_it complete (K_{it+1} group still in flight)
        __syncthreads();

        // O += P V   (P via intra-quad shuffle: C-frag -> A-frag layout)
        int sb = gid * 4 + (t4 >> 1);
        bool odd = (t4 & 1);
        #pragma unroll
        for (int kt = 0; kt < 16; kt++) {
            float v0 = __shfl_sync(0xffffffffu, s[kt][0], sb);
            float v1 = __shfl_sync(0xffffffffu, s[kt][1], sb);
            float v2 = __shfl_sync(0xffffffffu, s[kt][2], sb);
            float v3 = __shfl_sync(0xffffffffu, s[kt][3], sb);
            float w0 = __shfl_sync(0xffffffffu, s[kt][0], sb + 2);
            float w1 = __shfl_sync(0xffffffffu, s[kt][1], sb + 2);
            float w2 = __shfl_sync(0xffffffffu, s[kt][2], sb + 2);
            float w3 = __shfl_sync(0xffffffffu, s[kt][3], sb + 2);
            uint32_t a[4];
            a[0] = __float_as_uint(odd ? v1 : v0);
            a[1] = __float_as_uint(odd ? v3 : v2);
            a[2] = __float_as_uint(odd ? w1 : w0);
            a[3] = __float_as_uint(odd ? w3 : w2);
            int kr = kt * 8;
            #pragma unroll
            for (int nf = 0; nf < 16; nf++) {
                uint32_t b[2];
                b[0] = __float_as_uint(Vs[(kr + t4)     * STR + nf * 8 + gid]);
                b[1] = __float_as_uint(Vs[(kr + 4 + t4) * STR + nf * 8 + gid]);
                mma_tf32(o[nf], a, b);
            }
        }
        cp_wait<0>();      // K_{it+1} complete
        __syncthreads();   // Vs reads done before next V prefetch overwrites
    }

    // epilogue: divide by row sums, write att (tf32-rounded, feeds Wo gemm)
    lsum0 += __shfl_xor_sync(0xffffffffu, lsum0, 1);
    lsum0 += __shfl_xor_sync(0xffffffffu, lsum0, 2);
    lsum1 += __shfl_xor_sync(0xffffffffu, lsum1, 1);
    lsum1 += __shfl_xor_sync(0xffffffffu, lsum1, 2);
    float inv0 = 1.f / lsum0, inv1 = 1.f / lsum1;
    float* o0 = att + (size_t)me0 * DMODEL + h * DH + 2 * t4;
    float* o1 = att + (size_t)me1 * DMODEL + h * DH + 2 * t4;
    #pragma unroll
    for (int nf = 0; nf < 16; nf++) {
        *(float2*)(o0 + nf * 8) = make_float2(rnd_tf32(o[nf][0] * inv0), rnd_tf32(o[nf][1] * inv0));
        *(float2*)(o1 + nf * 8) = make_float2(rnd_tf32(o[nf][2] * inv1), rnd_tf32(o[nf][3] * inv1));
    }
}

extern "C" void kernel_launch(void* const* d_in, const int* in_sizes, int n_in,
                              void* d_out, int out_size) {
    (void)in_sizes; (void)n_in; (void)out_size;
    const float* x         = (const float*)d_in[0];
    const float* attn_bias = (const float*)d_in[1];
    const float* ln_scale  = (const float*)d_in[2];
    const float* ln_offset = (const float*)d_in[3];
    const float* Wq = (const float*)d_in[4];
    const float* Wk = (const float*)d_in[5];
    const float* Wv = (const float*)d_in[6];
    const float* Wo = (const float*)d_in[7];
    const float* W1 = (const float*)d_in[8];
    const float* b1 = (const float*)d_in[9];
    const float* W2 = (const float*)d_in[10];
    const float* b2 = (const float*)d_in[11];
    float* out = (float*)d_out;

    float *xn, *qkv, *att, *ff, *wqkv, *wo, *w1, *w2;
    cudaGetSymbolAddress((void**)&xn,   g_xn);
    cudaGetSymbolAddress((void**)&qkv,  g_qkv);
    cudaGetSymbolAddress((void**)&att,  g_att);
    cudaGetSymbolAddress((void**)&ff,   g_ff);
    cudaGetSymbolAddress((void**)&wqkv, g_wqkv);
    cudaGetSymbolAddress((void**)&wo,   g_wo);
    cudaGetSymbolAddress((void**)&w1,   g_w1);
    cudaGetSymbolAddress((void**)&w2,   g_w2);

    const int SM_NN = (4 * 128 * 20 + 4 * 16 * 136) * 4;   // 75776
    const int SM_FA = 3 * 128 * 132 * 4;                    // 202752
    cudaFuncSetAttribute(mma_gemm<0, 0>, cudaFuncAttributeMaxDynamicSharedMemorySize, SM_NN);
    cudaFuncSetAttribute(mma_gemm<0, 1>, cudaFuncAttributeMaxDynamicSharedMemorySize, SM_NN);
    cudaFuncSetAttribute(mma_gemm<1, 1>, cudaFuncAttributeMaxDynamicSharedMemorySize, SM_NN);
    cudaFuncSetAttribute(mma_gemm<2, 0>, cudaFuncAttributeMaxDynamicSharedMemorySize, SM_NN);
    cudaFuncSetAttribute(flash_kernel,   cudaFuncAttributeMaxDynamicSharedMemorySize, SM_FA);

    // 0. Round weights to tf32 (pack Wq|Wk|Wv)
    {
        int thr = 256;
        int nPack = DMODEL * (DMODEL / 4) * 3;
        int n4a = DMODEL * DMODEL / 4;
        int n4b = DMODEL * DFF / 4;
        cvt_pack3_kernel<<<(nPack + thr - 1) / thr, thr>>>(
            (const float4*)Wq, (const float4*)Wk, (const float4*)Wv, (float4*)wqkv);
        cvt_tf32_kernel<<<(n4a + thr - 1) / thr, thr>>>((const float4*)Wo, (float4*)wo, n4a);
        cvt_tf32_kernel<<<(n4b + thr - 1) / thr, thr>>>((const float4*)W1, (float4*)w1, n4b);
        cvt_tf32_kernel<<<(n4b + thr - 1) / thr, thr>>>((const float4*)W2, (float4*)w2, n4b);
    }

    // 1. LayerNorm
    ln_kernel<<<SEQ, 256>>>(x, ln_scale, ln_offset, xn);

    // 2. Fused QKV projection: [SEQ,2048] @ [2048,6144] -> qkv (tf32-rounded)
    mma_gemm<0, 1><<<dim3(3 * DMODEL / 128, SEQ / 128), 256, SM_NN>>>(
        xn, wqkv, nullptr, qkv, SEQ, 3 * DMODEL, DMODEL, DMODEL, 3 * DMODEL, 3 * DMODEL);

    // 3. RoPE (rounds q,k in place)
    rope_kernel<<<(SEQ * (DMODEL / 2) + 255) / 256, 256>>>(qkv);

    // 4. Flash attention -> att
    flash_kernel<<<dim3(SEQ / 128, NH), 256, SM_FA>>>(qkv, attn_bias, att);

    // 5. attn_out = att @ Wo -> d_out
    mma_gemm<0, 0><<<dim3(DMODEL / 128, SEQ / 128), 256, SM_NN>>>(
        att, wo, nullptr, out, SEQ, DMODEL, DMODEL, DMODEL, DMODEL, DMODEL);

    // 6. ff = gelu(xn @ W1 + b1)  (tf32-rounded)
    mma_gemm<1, 1><<<dim3(DFF / 128, SEQ / 128), 256, SM_NN>>>(
        xn, w1, b1, ff, SEQ, DFF, DMODEL, DMODEL, DFF, DFF);

    // 7. out += ff @ W2 + b2
    mma_gemm<2, 0><<<dim3(DMODEL / 128, SEQ / 128), 256, SM_NN>>>(
        ff, w2, b2, out, SEQ, DMODEL, DFF, DFF, DMODEL, DMODEL);
}

// round 8
// speedup vs baseline: 10.2898x; 1.5614x over previous
#include <cuda_runtime.h>
#include <cuda_fp16.h>
#include <math.h>
#include <stdint.h>

#define SEQ 2048
#define DMODEL 2048
#define NH 16
#define DH 128
#define DFF 8192
#define BOTTLE 1088   /* BACKGROUND_LEN + STYLE_VECS_LEN */
#define BG 1024       /* BACKGROUND_LEN */

// -------- scratch (no allocations allowed) --------
__device__ __half g_xnh[(size_t)SEQ * DMODEL];
__device__ float  g_qkv[(size_t)SEQ * 3 * DMODEL];
__device__ __half g_atth[(size_t)SEQ * DMODEL];
__device__ __half g_ffh[(size_t)SEQ * DFF];
// half TRANSPOSED weights ([N, K] layouts)
__device__ __half g_wqkvT[(size_t)3 * DMODEL * DMODEL];
__device__ __half g_woT[(size_t)DMODEL * DMODEL];
__device__ __half g_w1T[(size_t)DFF * DMODEL];
__device__ __half g_w2T[(size_t)DMODEL * DFF];

// -------- tf32 helpers (flash attention path) --------
__device__ __forceinline__ uint32_t f2tf32(float f) {
    uint32_t u;
    asm("cvt.rna.tf32.f32 %0, %1;" : "=r"(u) : "f"(f));
    return u;
}
__device__ __forceinline__ float rnd_tf32(float f) { return __uint_as_float(f2tf32(f)); }
__device__ __forceinline__ void mma_tf32(float c[4], const uint32_t a[4], const uint32_t b[2]) {
    asm volatile(
        "mma.sync.aligned.m16n8k8.row.col.f32.tf32.tf32.f32 "
        "{%0,%1,%2,%3}, {%4,%5,%6,%7}, {%8,%9}, {%0,%1,%2,%3};\n"
        : "+f"(c[0]), "+f"(c[1]), "+f"(c[2]), "+f"(c[3])
        : "r"(a[0]), "r"(a[1]), "r"(a[2]), "r"(a[3]), "r"(b[0]), "r"(b[1]));
}

// -------- fp16 mma + ldmatrix --------
__device__ __forceinline__ void mma_f16(float c[4], const uint32_t a[4], const uint32_t b0,
                                        const uint32_t b1) {
    asm volatile(
        "mma.sync.aligned.m16n8k16.row.col.f32.f16.f16.f32 "
        "{%0,%1,%2,%3}, {%4,%5,%6,%7}, {%8,%9}, {%0,%1,%2,%3};\n"
        : "+f"(c[0]), "+f"(c[1]), "+f"(c[2]), "+f"(c[3])
        : "r"(a[0]), "r"(a[1]), "r"(a[2]), "r"(a[3]), "r"(b0), "r"(b1));
}
__device__ __forceinline__ void ldsm4(uint32_t* r, uint32_t addr) {
    asm volatile("ldmatrix.sync.aligned.m8n8.x4.shared.b16 {%0,%1,%2,%3}, [%4];"
                 : "=r"(r[0]), "=r"(r[1]), "=r"(r[2]), "=r"(r[3]) : "r"(addr));
}

// -------- cp.async helpers --------
__device__ __forceinline__ void cp16(uint32_t s, const void* g) {
    asm volatile("cp.async.cg.shared.global [%0], [%1], 16;" :: "r"(s), "l"(g));
}
__device__ __forceinline__ void cp_commit() { asm volatile("cp.async.commit_group;"); }
template <int N> __device__ __forceinline__ void cp_wait() {
    asm volatile("cp.async.wait_group %0;" :: "n"(N));
}

// -------- reductions --------
__device__ __forceinline__ float blockReduceSum(float val) {
    __shared__ float sh[8];
    __shared__ float res;
    int lane = threadIdx.x & 31, w = threadIdx.x >> 5;
    #pragma unroll
    for (int o = 16; o > 0; o >>= 1) val += __shfl_xor_sync(0xffffffffu, val, o);
    if (lane == 0) sh[w] = val;
    __syncthreads();
    if (threadIdx.x == 0) {
        float s = 0.f;
        #pragma unroll
        for (int i = 0; i < 8; i++) s += sh[i];
        res = s;
    }
    __syncthreads();
    float r = res;
    __syncthreads();
    return r;
}

// -------- transpose + fp16 convert: out[N,K] = half(in[K,N]^T) --------
__global__ void cvt_T_kernel(const float* __restrict__ in, __half* __restrict__ out,
                             int K, int N) {
    __shared__ float tile[32][33];
    int bx = blockIdx.x * 32;  // N
    int by = blockIdx.y * 32;  // K
    int x = threadIdx.x, y = threadIdx.y;
    #pragma unroll
    for (int i = 0; i < 32; i += 8)
        tile[y + i][x] = in[(size_t)(by + y + i) * N + bx + x];
    __syncthreads();
    #pragma unroll
    for (int i = 0; i < 32; i += 8)
        out[(size_t)(bx + y + i) * K + by + x] = __float2half_rn(tile[x][y + i]);
}

// -------- LayerNorm (half output; it only feeds fp16 GEMMs) --------
__global__ void ln_kernel(const float* __restrict__ x, const float* __restrict__ sc,
                          const float* __restrict__ of, __half* __restrict__ out) {
    int row = blockIdx.x;
    const float* xr = x + (size_t)row * DMODEL;
    __half* o = out + (size_t)row * DMODEL;
    float s = 0.f, s2 = 0.f;
    for (int i = threadIdx.x; i < DMODEL; i += blockDim.x) {
        float v = xr[i];
        s += v; s2 += v * v;
    }
    s  = blockReduceSum(s);
    s2 = blockReduceSum(s2);
    float mean = s / DMODEL;
    float var  = s2 / DMODEL - mean * mean;
    float r = rsqrtf(var + 1e-5f);
    for (int i = threadIdx.x; i < DMODEL; i += blockDim.x)
        o[i] = __float2half_rn(sc[i] * r * (xr[i] - mean) + of[i]);
}

// -------- RoPE on packed qkv (fp32), tf32-rounded for flash --------
__global__ void rope_kernel(float* __restrict__ qkv) {
    int idx = blockIdx.x * blockDim.x + threadIdx.x;
    if (idx >= SEQ * (DMODEL / 2)) return;
    int t = idx / (DMODEL / 2);
    int r = idx % (DMODEL / 2);
    int h = r / (DH / 2);
    int i = r % (DH / 2);
    float inv = powf(10000.0f, -(float)(2 * i) / (float)DH);
    float ang = (float)t * inv;
    float s, c;
    sincosf(ang, &s, &c);
    size_t base = (size_t)t * (3 * DMODEL) + (size_t)h * DH + 2 * i;
    float q0 = qkv[base], q1 = qkv[base + 1];
    qkv[base]     = rnd_tf32(q0 * c - q1 * s);
    qkv[base + 1] = rnd_tf32(q1 * c + q0 * s);
    size_t kb = base + DMODEL;
    float k0 = qkv[kb], k1 = qkv[kb + 1];
    qkv[kb]     = rnd_tf32(k0 * c - k1 * s);
    qkv[kb + 1] = rnd_tf32(k1 * c + k0 * s);
}

__device__ __forceinline__ float gelu_f(float x) {
    float x3 = x * x * x;
    return 0.5f * x * (1.0f + tanhf(0.7978845608028654f * (x + 0.044715f * x3)));
}

// ============ FP16 tensor-core GEMM (fp32 accum), ldmatrix + cp.async 4-stage ============
// C[m,n] = sum_k A[m,k] * Bt[n,k]; A: half [M,K] rm, Bt: half [N,K] rm.
// EPI 0: v = acc   EPI 1: v = gelu(acc + bias[n])   EPI 2: v = C[idx] + acc + bias[n]
// OUTH: write half to Ch (instead of float to C).  ROUND: tf32-rna round fp32 output.
template <int EPI, int OUTH, int ROUND>
__global__ __launch_bounds__(256, 2)
void hgemm(const __half* __restrict__ A, const __half* __restrict__ Bt,
           const float* __restrict__ bias, float* __restrict__ C,
           __half* __restrict__ Ch, int K, int ldc) {
    constexpr int S = 4, BK = 32;             // 32 halves of K per stage
    constexpr int LDA = 40;                    // halves per smem row (pad 8)
    constexpr int STAGE = 128 * LDA;           // halves per operand stage

    extern __shared__ __half smh[];
    __half* Asm = smh;
    __half* Bsm = smh + S * STAGE;

    int t = threadIdx.x;
    int m0 = blockIdx.y * 128, n0 = blockIdx.x * 128;
    int lane = t & 31, warp = t >> 5;
    int wm = (warp >> 2) * 64;    // 0 / 64
    int wn = (warp & 3) * 32;     // 0,32,64,96
    int gid = lane >> 2, t4 = lane & 3;

    float acc[4][4][4];
    #pragma unroll
    for (int f = 0; f < 4; f++)
        #pragma unroll
        for (int g = 0; g < 4; g++)
            #pragma unroll
            for (int e = 0; e < 4; e++) acc[f][g][e] = 0.f;

    // cp.async indexing: 512 16B-chunks per operand stage; row = cid>>2, chunk c = cid&3
    uint32_t aBase = (uint32_t)__cvta_generic_to_shared(Asm);
    uint32_t bBase = (uint32_t)__cvta_generic_to_shared(Bsm);
    int r0c = t >> 2, c0c = t & 3;             // chunk 0 of this thread
    int r1c = (t + 256) >> 2, c1c = t & 3;     // chunk 1

    int nt = K / BK;

    auto load_stage = [&](int s, int kt) {
        int k0 = kt * BK;
        uint32_t as = aBase + s * STAGE * 2;
        uint32_t bs = bBase + s * STAGE * 2;
        cp16(as + r0c * 80 + c0c * 16, A + (size_t)(m0 + r0c) * K + k0 + c0c * 8);
        cp16(as + r1c * 80 + c1c * 16, A + (size_t)(m0 + r1c) * K + k0 + c1c * 8);
        cp16(bs + r0c * 80 + c0c * 16, Bt + (size_t)(n0 + r0c) * K + k0 + c0c * 8);
        cp16(bs + r1c * 80 + c1c * 16, Bt + (size_t)(n0 + r1c) * K + k0 + c1c * 8);
    };

    #pragma unroll
    for (int s = 0; s < S - 1; s++) {
        if (s < nt) load_stage(s, s);
        cp_commit();
    }

    // ldmatrix per-lane row/col offsets (same formula for A and B tiles)
    int lj = lane & 7;
    int lrow = lj + ((lane >> 3) & 1) * 8;   // row within 16-row group
    int lcol = (lane >> 4) * 8;              // 0 or 8 (k offset)

    for (int kt = 0; kt < nt; kt++) {
        cp_wait<S - 2>();
        __syncthreads();
        int nx = kt + S - 1;
        if (nx < nt) load_stage(nx & (S - 1), nx);
        cp_commit();

        uint32_t as = aBase + (kt & (S - 1)) * STAGE * 2;
        uint32_t bs = bBase + (kt & (S - 1)) * STAGE * 2;

        #pragma unroll
        for (int kk = 0; kk < BK; kk += 16) {
            uint32_t af[4][4];
            #pragma unroll
            for (int f = 0; f < 4; f++)
                ldsm4(af[f], as + ((wm + f * 16 + lrow) * LDA + kk + lcol) * 2);
            uint32_t bf[2][4];
            #pragma unroll
            for (int g2 = 0; g2 < 2; g2++)
                ldsm4(bf[g2], bs + ((wn + g2 * 16 + lrow) * LDA + kk + lcol) * 2);
            #pragma unroll
            for (int f = 0; f < 4; f++) {
                mma_f16(acc[f][0], af[f], bf[0][0], bf[0][2]);
                mma_f16(acc[f][1], af[f], bf[0][1], bf[0][3]);
                mma_f16(acc[f][2], af[f], bf[1][0], bf[1][2]);
                mma_f16(acc[f][3], af[f], bf[1][1], bf[1][3]);
            }
        }
    }

    // epilogue (m16n8 C-frag layout)
    #pragma unroll
    for (int f = 0; f < 4; f++) {
        #pragma unroll
        for (int g = 0; g < 4; g++) {
            #pragma unroll
            for (int half = 0; half < 2; half++) {
                int m = m0 + wm + f * 16 + gid + half * 8;
                int n = n0 + wn + g * 8 + 2 * t4;
                float v0 = acc[f][g][half * 2 + 0];
                float v1 = acc[f][g][half * 2 + 1];
                size_t idx = (size_t)m * ldc + n;
                if (EPI == 1) {
                    v0 = gelu_f(v0 + bias[n]);
                    v1 = gelu_f(v1 + bias[n + 1]);
                } else if (EPI == 2) {
                    v0 = C[idx]     + v0 + bias[n];
                    v1 = C[idx + 1] + v1 + bias[n + 1];
                }
                if (OUTH) {
                    *(__half2*)(Ch + idx) = __floats2half2_rn(v0, v1);
                } else {
                    if (ROUND) { v0 = rnd_tf32(v0); v1 = rnd_tf32(v1); }
                    C[idx]     = v0;
                    C[idx + 1] = v1;
                }
            }
        }
    }
}

// ============ Flash attention (tf32 mma.sync, online softmax) ============
__global__ void __launch_bounds__(256, 1)
flash_kernel(const float* __restrict__ qkv, const float* __restrict__ bias,
             __half* __restrict__ att) {
    constexpr int LD = 3 * DMODEL;
    constexpr int STR = 132;
    extern __shared__ float sm[];
    float* Qs = sm;
    float* Ks = sm + 128 * STR;
    float* Vs = sm + 2 * 128 * STR;

    int mb = blockIdx.x, h = blockIdx.y;
    int m0 = mb * 128;
    int t = threadIdx.x, lane = t & 31, warp = t >> 5;
    int gid = lane >> 2, t4 = lane & 3;
    int wrow = warp * 16;

    const float* kbase = qkv + DMODEL + h * DH;
    const float* vbase = qkv + 2 * DMODEL + h * DH;

    int lr = t >> 1, lc = (t & 1) * 64;

    int it0 = (m0 >= 1152) ? 8 : 0;
    {
        const float* g = qkv + (size_t)(m0 + lr) * LD + h * DH + lc;
        uint32_t s = (uint32_t)__cvta_generic_to_shared(Qs + lr * STR + lc);
        #pragma unroll
        for (int i = 0; i < 16; i++) cp16(s + i * 16, g + i * 4);
    }
    {
        const float* g = kbase + (size_t)(it0 * 128 + lr) * LD + lc;
        uint32_t s = (uint32_t)__cvta_generic_to_shared(Ks + lr * STR + lc);
        #pragma unroll
        for (int i = 0; i < 16; i++) cp16(s + i * 16, g + i * 4);
    }
    cp_commit();
    cp_wait<0>();
    __syncthreads();

    float o[16][4];
    #pragma unroll
    for (int g = 0; g < 16; g++) { o[g][0] = o[g][1] = o[g][2] = o[g][3] = 0.f; }
    float mrow0 = -INFINITY, mrow1 = -INFINITY;
    float lsum0 = 0.f, lsum1 = 0.f;

    const float scale = 0.08838834764831845f;
    int me0 = m0 + wrow + gid;
    int me1 = me0 + 8;

    for (int it = it0; it <= mb; it++) {
        int n0 = it * 128;

        {
            const float* g = vbase + (size_t)(n0 + lr) * LD + lc;
            uint32_t s = (uint32_t)__cvta_generic_to_shared(Vs + lr * STR + lc);
            #pragma unroll
            for (int i = 0; i < 16; i++) cp16(s + i * 16, g + i * 4);
            cp_commit();
        }

        float s[16][4];
        #pragma unroll
        for (int g = 0; g < 16; g++) s[g][0] = s[g][1] = s[g][2] = s[g][3] = 0.f;

        #pragma unroll
        for (int kt = 0; kt < 16; kt++) {
            uint32_t a[4];
            int kc = kt * 8;
            a[0] = __float_as_uint(Qs[(wrow + gid)     * STR + kc + t4]);
            a[1] = __float_as_uint(Qs[(wrow + gid + 8) * STR + kc + t4]);
            a[2] = __float_as_uint(Qs[(wrow + gid)     * STR + kc + 4 + t4]);
            a[3] = __float_as_uint(Qs[(wrow + gid + 8) * STR + kc + 4 + t4]);
            #pragma unroll
            for (int g = 0; g < 16; g++) {
                uint32_t b[2];
                b[0] = __float_as_uint(Ks[(g * 8 + gid) * STR + kc + t4]);
                b[1] = __float_as_uint(Ks[(g * 8 + gid) * STR + kc + 4 + t4]);
                mma_tf32(s[g], a, b);
            }
        }
        __syncthreads();

        if (it < mb) {
            const float* g = kbase + (size_t)(n0 + 128 + lr) * LD + lc;
            uint32_t sa = (uint32_t)__cvta_generic_to_shared(Ks + lr * STR + lc);
            #pragma unroll
            for (int i = 0; i < 16; i++) cp16(sa + i * 16, g + i * 4);
        }
        cp_commit();

        float mx0 = -INFINITY, mx1 = -INFINITY;
        const float* bp0 = bias + (size_t)me0 * SEQ + n0 + 2 * t4;
        const float* bp1 = bias + (size_t)me1 * SEQ + n0 + 2 * t4;
        #pragma unroll
        for (int g = 0; g < 16; g++) {
            int nc = n0 + g * 8 + 2 * t4;
            float2 b0 = *(const float2*)(bp0 + g * 8);
            float2 b1 = *(const float2*)(bp1 + g * 8);
            bool a00 = (nc     <= me0) && !((me0 >= BOTTLE) && (nc     < BG));
            bool a01 = (nc + 1 <= me0) && !((me0 >= BOTTLE) && (nc + 1 < BG));
            bool a10 = (nc     <= me1) && !((me1 >= BOTTLE) && (nc     < BG));
            bool a11 = (nc + 1 <= me1) && !((me1 >= BOTTLE) && (nc + 1 < BG));
            s[g][0] = s[g][0] * scale + (a00 ? 0.f : -1e10f) + b0.x;
            s[g][1] = s[g][1] * scale + (a01 ? 0.f : -1e10f) + b0.y;
            s[g][2] = s[g][2] * scale + (a10 ? 0.f : -1e10f) + b1.x;
            s[g][3] = s[g][3] * scale + (a11 ? 0.f : -1e10f) + b1.y;
            mx0 = fmaxf(mx0, fmaxf(s[g][0], s[g][1]));
            mx1 = fmaxf(mx1, fmaxf(s[g][2], s[g][3]));
        }
        mx0 = fmaxf(mx0, __shfl_xor_sync(0xffffffffu, mx0, 1));
        mx0 = fmaxf(mx0, __shfl_xor_sync(0xffffffffu, mx0, 2));
        mx1 = fmaxf(mx1, __shfl_xor_sync(0xffffffffu, mx1, 1));
        mx1 = fmaxf(mx1, __shfl_xor_sync(0xffffffffu, mx1, 2));
        float mn0 = fmaxf(mrow0, mx0), mn1 = fmaxf(mrow1, mx1);
        float al0 = __expf(mrow0 - mn0), al1 = __expf(mrow1 - mn1);
        float rs0 = 0.f, rs1 = 0.f;
        #pragma unroll
        for (int g = 0; g < 16; g++) {
            float p0 = __expf(s[g][0] - mn0), p1 = __expf(s[g][1] - mn0);
            float p2 = __expf(s[g][2] - mn1), p3 = __expf(s[g][3] - mn1);
            rs0 += p0 + p1; rs1 += p2 + p3;
            s[g][0] = rnd_tf32(p0); s[g][1] = rnd_tf32(p1);
            s[g][2] = rnd_tf32(p2); s[g][3] = rnd_tf32(p3);
        }
        lsum0 = lsum0 * al0 + rs0;
        lsum1 = lsum1 * al1 + rs1;
        mrow0 = mn0; mrow1 = mn1;
        #pragma unroll
        for (int g = 0; g < 16; g++) {
            o[g][0] *= al0; o[g][1] *= al0; o[g][2] *= al1; o[g][3] *= al1;
        }

        cp_wait<1>();
        __syncthreads();

        int sb = gid * 4 + (t4 >> 1);
        bool odd = (t4 & 1);
        #pragma unroll
        for (int kt = 0; kt < 16; kt++) {
            float v0 = __shfl_sync(0xffffffffu, s[kt][0], sb);
            float v1 = __shfl_sync(0xffffffffu, s[kt][1], sb);
            float v2 = __shfl_sync(0xffffffffu, s[kt][2], sb);
            float v3 = __shfl_sync(0xffffffffu, s[kt][3], sb);
            float w0 = __shfl_sync(0xffffffffu, s[kt][0], sb + 2);
            float w1 = __shfl_sync(0xffffffffu, s[kt][1], sb + 2);
            float w2 = __shfl_sync(0xffffffffu, s[kt][2], sb + 2);
            float w3 = __shfl_sync(0xffffffffu, s[kt][3], sb + 2);
            uint32_t a[4];
            a[0] = __float_as_uint(odd ? v1 : v0);
            a[1] = __float_as_uint(odd ? v3 : v2);
            a[2] = __float_as_uint(odd ? w1 : w0);
            a[3] = __float_as_uint(odd ? w3 : w2);
            int kr = kt * 8;
            #pragma unroll
            for (int nf = 0; nf < 16; nf++) {
                uint32_t b[2];
                b[0] = __float_as_uint(Vs[(kr + t4)     * STR + nf * 8 + gid]);
                b[1] = __float_as_uint(Vs[(kr + 4 + t4) * STR + nf * 8 + gid]);
                mma_tf32(o[nf], a, b);
            }
        }
        cp_wait<0>();
        __syncthreads();
    }

    lsum0 += __shfl_xor_sync(0xffffffffu, lsum0, 1);
    lsum0 += __shfl_xor_sync(0xffffffffu, lsum0, 2);
    lsum1 += __shfl_xor_sync(0xffffffffu, lsum1, 1);
    lsum1 += __shfl_xor_sync(0xffffffffu, lsum1, 2);
    float inv0 = 1.f / lsum0, inv1 = 1.f / lsum1;
    __half* o0 = att + (size_t)me0 * DMODEL + h * DH + 2 * t4;
    __half* o1 = att + (size_t)me1 * DMODEL + h * DH + 2 * t4;
    #pragma unroll
    for (int nf = 0; nf < 16; nf++) {
        *(__half2*)(o0 + nf * 8) = __floats2half2_rn(o[nf][0] * inv0, o[nf][1] * inv0);
        *(__half2*)(o1 + nf * 8) = __floats2half2_rn(o[nf][2] * inv1, o[nf][3] * inv1);
    }
}

extern "C" void kernel_launch(void* const* d_in, const int* in_sizes, int n_in,
                              void* d_out, int out_size) {
    (void)in_sizes; (void)n_in; (void)out_size;
    const float* x         = (const float*)d_in[0];
    const float* attn_bias = (const float*)d_in[1];
    const float* ln_scale  = (const float*)d_in[2];
    const float* ln_offset = (const float*)d_in[3];
    const float* Wq = (const float*)d_in[4];
    const float* Wk = (const float*)d_in[5];
    const float* Wv = (const float*)d_in[6];
    const float* Wo = (const float*)d_in[7];
    const float* W1 = (const float*)d_in[8];
    const float* b1 = (const float*)d_in[9];
    const float* W2 = (const float*)d_in[10];
    const float* b2 = (const float*)d_in[11];
    float* out = (float*)d_out;

    __half *xnh, *atth, *ffh, *wqkvT, *woT, *w1T, *w2T;
    float *qkv;
    cudaGetSymbolAddress((void**)&xnh,   g_xnh);
    cudaGetSymbolAddress((void**)&qkv,   g_qkv);
    cudaGetSymbolAddress((void**)&atth,  g_atth);
    cudaGetSymbolAddress((void**)&ffh,   g_ffh);
    cudaGetSymbolAddress((void**)&wqkvT, g_wqkvT);
    cudaGetSymbolAddress((void**)&woT,   g_woT);
    cudaGetSymbolAddress((void**)&w1T,   g_w1T);
    cudaGetSymbolAddress((void**)&w2T,   g_w2T);

    const int SM_HG = 4 * 2 * 128 * 40 * 2;     // 4 stages * (A+B) * 128*40 halves = 81920 B
    const int SM_FA = 3 * 128 * 132 * 4;         // 202752 B
    cudaFuncSetAttribute(hgemm<0, 0, 1>, cudaFuncAttributeMaxDynamicSharedMemorySize, SM_HG);
    cudaFuncSetAttribute(hgemm<0, 0, 0>, cudaFuncAttributeMaxDynamicSharedMemorySize, SM_HG);
    cudaFuncSetAttribute(hgemm<1, 1, 0>, cudaFuncAttributeMaxDynamicSharedMemorySize, SM_HG);
    cudaFuncSetAttribute(hgemm<2, 0, 0>, cudaFuncAttributeMaxDynamicSharedMemorySize, SM_HG);
    cudaFuncSetAttribute(flash_kernel, cudaFuncAttributeMaxDynamicSharedMemorySize, SM_FA);

    // 0. Transpose + fp16-convert weights -> [N,K]
    {
        dim3 b(32, 8);
        cvt_T_kernel<<<dim3(DMODEL / 32, DMODEL / 32), b>>>(Wq, wqkvT, DMODEL, DMODEL);
        cvt_T_kernel<<<dim3(DMODEL / 32, DMODEL / 32), b>>>(Wk, wqkvT + (size_t)DMODEL * DMODEL, DMODEL, DMODEL);
        cvt_T_kernel<<<dim3(DMODEL / 32, DMODEL / 32), b>>>(Wv, wqkvT + (size_t)2 * DMODEL * DMODEL, DMODEL, DMODEL);
        cvt_T_kernel<<<dim3(DMODEL / 32, DMODEL / 32), b>>>(Wo, woT, DMODEL, DMODEL);
        cvt_T_kernel<<<dim3(DFF / 32, DMODEL / 32), b>>>(W1, w1T, DMODEL, DFF);
        cvt_T_kernel<<<dim3(DMODEL / 32, DFF / 32), b>>>(W2, w2T, DFF, DMODEL);
    }

    // 1. LayerNorm -> xn half
    ln_kernel<<<SEQ, 256>>>(x, ln_scale, ln_offset, xnh);

    // 2. Fused QKV projection -> qkv fp32 (tf32-rounded for flash)
    hgemm<0, 0, 1><<<dim3(3 * DMODEL / 128, SEQ / 128), 256, SM_HG>>>(
        xnh, wqkvT, nullptr, qkv, nullptr, DMODEL, 3 * DMODEL);

    // 3. RoPE
    rope_kernel<<<(SEQ * (DMODEL / 2) + 255) / 256, 256>>>(qkv);

    // 4. Flash attention -> att half
    flash_kernel<<<dim3(SEQ / 128, NH), 256, SM_FA>>>(qkv, attn_bias, atth);

    // 5. attn_out = att @ Wo -> d_out (fp32)
    hgemm<0, 0, 0><<<dim3(DMODEL / 128, SEQ / 128), 256, SM_HG>>>(
        atth, woT, nullptr, out, nullptr, DMODEL, DMODEL);

    // 6. ff = gelu(xn @ W1 + b1) -> half
    hgemm<1, 1, 0><<<dim3(DFF / 128, SEQ / 128), 256, SM_HG>>>(
        xnh, w1T, b1, nullptr, ffh, DMODEL, DFF);

    // 7. out += ff @ W2 + b2
    hgemm<2, 0, 0><<<dim3(DMODEL / 128, SEQ / 128), 256, SM_HG>>>(
        ffh, w2T, b2, out, nullptr, DFF, DMODEL);
}

// round 10
// speedup vs baseline: 11.2985x; 1.0980x over previous
#include <cuda_runtime.h>
#include <cuda_fp16.h>
#include <math.h>
#include <stdint.h>

#define SEQ 2048
#define DMODEL 2048
#define NH 16
#define DH 128
#define DFF 8192
#define BOTTLE 1088   /* BACKGROUND_LEN + STYLE_VECS_LEN */
#define BG 1024       /* BACKGROUND_LEN */

// -------- scratch (no allocations allowed) --------
__device__ __half g_xnh[(size_t)SEQ * DMODEL];
__device__ __half g_qkvh[(size_t)SEQ * 3 * DMODEL];
__device__ __half g_atth[(size_t)SEQ * DMODEL];
__device__ __half g_ffh[(size_t)SEQ * DFF];
// half TRANSPOSED weights ([N, K] layouts)
__device__ __half g_wqkvT[(size_t)3 * DMODEL * DMODEL];
__device__ __half g_woT[(size_t)DMODEL * DMODEL];
__device__ __half g_w1T[(size_t)DFF * DMODEL];
__device__ __half g_w2T[(size_t)DMODEL * DFF];

// -------- fp16 mma + ldmatrix --------
__device__ __forceinline__ void mma_f16(float c[4], const uint32_t a[4], const uint32_t b0,
                                        const uint32_t b1) {
    asm volatile(
        "mma.sync.aligned.m16n8k16.row.col.f32.f16.f16.f32 "
        "{%0,%1,%2,%3}, {%4,%5,%6,%7}, {%8,%9}, {%0,%1,%2,%3};\n"
        : "+f"(c[0]), "+f"(c[1]), "+f"(c[2]), "+f"(c[3])
        : "r"(a[0]), "r"(a[1]), "r"(a[2]), "r"(a[3]), "r"(b0), "r"(b1));
}
__device__ __forceinline__ void ldsm4(uint32_t* r, uint32_t addr) {
    asm volatile("ldmatrix.sync.aligned.m8n8.x4.shared.b16 {%0,%1,%2,%3}, [%4];"
                 : "=r"(r[0]), "=r"(r[1]), "=r"(r[2]), "=r"(r[3]) : "r"(addr));
}
__device__ __forceinline__ void ldsm4t(uint32_t* r, uint32_t addr) {
    asm volatile("ldmatrix.sync.aligned.m8n8.x4.trans.shared.b16 {%0,%1,%2,%3}, [%4];"
                 : "=r"(r[0]), "=r"(r[1]), "=r"(r[2]), "=r"(r[3]) : "r"(addr));
}
// pack two fp32 -> one fp16x2 register (lo = a, hi = b)
__device__ __forceinline__ uint32_t packh2(float a, float b) {
    uint32_t r;
    asm("cvt.rn.f16x2.f32 %0, %2, %1;" : "=r"(r) : "f"(a), "f"(b));
    return r;
}

// -------- cp.async helpers --------
__device__ __forceinline__ void cp16(uint32_t s, const void* g) {
    asm volatile("cp.async.cg.shared.global [%0], [%1], 16;" :: "r"(s), "l"(g));
}
__device__ __forceinline__ void cp_commit() { asm volatile("cp.async.commit_group;"); }
template <int N> __device__ __forceinline__ void cp_wait() {
    asm volatile("cp.async.wait_group %0;" :: "n"(N));
}

// -------- reductions --------
__device__ __forceinline__ float blockReduceSum(float val) {
    __shared__ float sh[8];
    __shared__ float res;
    int lane = threadIdx.x & 31, w = threadIdx.x >> 5;
    #pragma unroll
    for (int o = 16; o > 0; o >>= 1) val += __shfl_xor_sync(0xffffffffu, val, o);
    if (lane == 0) sh[w] = val;
    __syncthreads();
    if (threadIdx.x == 0) {
        float s = 0.f;
        #pragma unroll
        for (int i = 0; i < 8; i++) s += sh[i];
        res = s;
    }
    __syncthreads();
    float r = res;
    __syncthreads();
    return r;
}

// -------- transpose + fp16 convert: out[N,K] = half(in[K,N]^T) --------
__global__ void cvt_T_kernel(const float* __restrict__ in, __half* __restrict__ out,
                             int K, int N) {
    __shared__ float tile[32][33];
    int bx = blockIdx.x * 32;  // N
    int by = blockIdx.y * 32;  // K
    int x = threadIdx.x, y = threadIdx.y;
    #pragma unroll
    for (int i = 0; i < 32; i += 8)
        tile[y + i][x] = in[(size_t)(by + y + i) * N + bx + x];
    __syncthreads();
    #pragma unroll
    for (int i = 0; i < 32; i += 8)
        out[(size_t)(bx + y + i) * K + by + x] = __float2half_rn(tile[x][y + i]);
}

// -------- LayerNorm (half output) --------
__global__ void ln_kernel(const float* __restrict__ x, const float* __restrict__ sc,
                          const float* __restrict__ of, __half* __restrict__ out) {
    int row = blockIdx.x;
    const float* xr = x + (size_t)row * DMODEL;
    __half* o = out + (size_t)row * DMODEL;
    float s = 0.f, s2 = 0.f;
    for (int i = threadIdx.x; i < DMODEL; i += blockDim.x) {
        float v = xr[i];
        s += v; s2 += v * v;
    }
    s  = blockReduceSum(s);
    s2 = blockReduceSum(s2);
    float mean = s / DMODEL;
    float var  = s2 / DMODEL - mean * mean;
    float r = rsqrtf(var + 1e-5f);
    for (int i = threadIdx.x; i < DMODEL; i += blockDim.x)
        o[i] = __float2half_rn(sc[i] * r * (xr[i] - mean) + of[i]);
}

// -------- RoPE on packed half qkv (q at 0, k at DMODEL) --------
__global__ void rope_kernel(__half* __restrict__ qkv) {
    int idx = blockIdx.x * blockDim.x + threadIdx.x;
    if (idx >= SEQ * (DMODEL / 2)) return;
    int t = idx / (DMODEL / 2);
    int r = idx % (DMODEL / 2);
    int h = r / (DH / 2);
    int i = r % (DH / 2);
    float inv = powf(10000.0f, -(float)(2 * i) / (float)DH);
    float ang = (float)t * inv;
    float s, c;
    sincosf(ang, &s, &c);
    size_t base = (size_t)t * (3 * DMODEL) + (size_t)h * DH + 2 * i;
    __half2* qp = (__half2*)(qkv + base);
    float2 q = __half22float2(*qp);
    *qp = __floats2half2_rn(q.x * c - q.y * s, q.y * c + q.x * s);
    __half2* kp = (__half2*)(qkv + base + DMODEL);
    float2 k = __half22float2(*kp);
    *kp = __floats2half2_rn(k.x * c - k.y * s, k.y * c + k.x * s);
}

__device__ __forceinline__ float gelu_f(float x) {
    float x3 = x * x * x;
    return 0.5f * x * (1.0f + tanhf(0.7978845608028654f * (x + 0.044715f * x3)));
}

// ============ FP16 tensor-core GEMM (fp32 accum), ldmatrix + cp.async 4-stage ============
// EPI 0: v = acc   EPI 1: v = gelu(acc + bias[n])   EPI 2: v = C[idx] + acc + bias[n]
// OUTH: write half to Ch.
template <int EPI, int OUTH>
__global__ __launch_bounds__(256, 2)
void hgemm(const __half* __restrict__ A, const __half* __restrict__ Bt,
           const float* __restrict__ bias, float* __restrict__ C,
           __half* __restrict__ Ch, int K, int ldc) {
    constexpr int S = 4, BK = 32;
    constexpr int LDA = 40;
    constexpr int STAGE = 128 * LDA;

    extern __shared__ __half smh[];
    __half* Asm = smh;
    __half* Bsm = smh + S * STAGE;

    int t = threadIdx.x;
    int m0 = blockIdx.y * 128, n0 = blockIdx.x * 128;
    int lane = t & 31, warp = t >> 5;
    int wm = (warp >> 2) * 64;
    int wn = (warp & 3) * 32;
    int gid = lane >> 2, t4 = lane & 3;

    float acc[4][4][4];
    #pragma unroll
    for (int f = 0; f < 4; f++)
        #pragma unroll
        for (int g = 0; g < 4; g++)
            #pragma unroll
            for (int e = 0; e < 4; e++) acc[f][g][e] = 0.f;

    uint32_t aBase = (uint32_t)__cvta_generic_to_shared(Asm);
    uint32_t bBase = (uint32_t)__cvta_generic_to_shared(Bsm);
    int r0c = t >> 2, c0c = t & 3;
    int r1c = (t + 256) >> 2, c1c = t & 3;

    int nt = K / BK;

    auto load_stage = [&](int s, int kt) {
        int k0 = kt * BK;
        uint32_t as = aBase + s * STAGE * 2;
        uint32_t bs = bBase + s * STAGE * 2;
        cp16(as + r0c * 80 + c0c * 16, A + (size_t)(m0 + r0c) * K + k0 + c0c * 8);
        cp16(as + r1c * 80 + c1c * 16, A + (size_t)(m0 + r1c) * K + k0 + c1c * 8);
        cp16(bs + r0c * 80 + c0c * 16, Bt + (size_t)(n0 + r0c) * K + k0 + c0c * 8);
        cp16(bs + r1c * 80 + c1c * 16, Bt + (size_t)(n0 + r1c) * K + k0 + c1c * 8);
    };

    #pragma unroll
    for (int s = 0; s < S - 1; s++) {
        if (s < nt) load_stage(s, s);
        cp_commit();
    }

    int lrow = (lane & 7) + ((lane >> 3) & 1) * 8;
    int lcol = (lane >> 4) * 8;

    for (int kt = 0; kt < nt; kt++) {
        cp_wait<S - 2>();
        __syncthreads();
        int nx = kt + S - 1;
        if (nx < nt) load_stage(nx & (S - 1), nx);
        cp_commit();

        uint32_t as = aBase + (kt & (S - 1)) * STAGE * 2;
        uint32_t bs = bBase + (kt & (S - 1)) * STAGE * 2;

        #pragma unroll
        for (int kk = 0; kk < BK; kk += 16) {
            uint32_t af[4][4];
            #pragma unroll
            for (int f = 0; f < 4; f++)
                ldsm4(af[f], as + ((wm + f * 16 + lrow) * LDA + kk + lcol) * 2);
            uint32_t bf[2][4];
            #pragma unroll
            for (int g2 = 0; g2 < 2; g2++)
                ldsm4(bf[g2], bs + ((wn + g2 * 16 + lrow) * LDA + kk + lcol) * 2);
            #pragma unroll
            for (int f = 0; f < 4; f++) {
                mma_f16(acc[f][0], af[f], bf[0][0], bf[0][2]);
                mma_f16(acc[f][1], af[f], bf[0][1], bf[0][3]);
                mma_f16(acc[f][2], af[f], bf[1][0], bf[1][2]);
                mma_f16(acc[f][3], af[f], bf[1][1], bf[1][3]);
            }
        }
    }

    #pragma unroll
    for (int f = 0; f < 4; f++) {
        #pragma unroll
        for (int g = 0; g < 4; g++) {
            #pragma unroll
            for (int half = 0; half < 2; half++) {
                int m = m0 + wm + f * 16 + gid + half * 8;
                int n = n0 + wn + g * 8 + 2 * t4;
                float v0 = acc[f][g][half * 2 + 0];
                float v1 = acc[f][g][half * 2 + 1];
                size_t idx = (size_t)m * ldc + n;
                if (EPI == 1) {
                    v0 = gelu_f(v0 + bias[n]);
                    v1 = gelu_f(v1 + bias[n + 1]);
                } else if (EPI == 2) {
                    v0 = C[idx]     + v0 + bias[n];
                    v1 = C[idx + 1] + v1 + bias[n + 1];
                }
                if (OUTH) {
                    *(uint32_t*)(Ch + idx) = packh2(v0, v1);
                } else {
                    C[idx]     = v0;
                    C[idx + 1] = v1;
                }
            }
        }
    }
}

// ============ FP16 flash attention (m16n8k16 mma, ldmatrix, online softmax) ============
// 256 threads = 8 warps; warp owns 16 q-rows x 128 kv-cols. Q/K/V half tiles 128x136.
__global__ void __launch_bounds__(256, 1)
flash_kernel(const __half* __restrict__ qkv, const float* __restrict__ bias,
             __half* __restrict__ att) {
    constexpr int LD = 3 * DMODEL;
    constexpr int STR = 136;                 // halves per smem row
    extern __shared__ __half smh[];
    __half* Qs = smh;
    __half* Ks = smh + 128 * STR;
    __half* Vs = smh + 2 * 128 * STR;
    uint32_t qB = (uint32_t)__cvta_generic_to_shared(Qs);
    uint32_t kB = (uint32_t)__cvta_generic_to_shared(Ks);
    uint32_t vB = (uint32_t)__cvta_generic_to_shared(Vs);

    int mb = blockIdx.x, h = blockIdx.y;
    int m0 = mb * 128;
    int t = threadIdx.x, lane = t & 31, warp = t >> 5;
    int gid = lane >> 2, t4 = lane & 3;
    int wrow = warp * 16;

    const __half* kbase = qkv + DMODEL + h * DH;
    const __half* vbase = qkv + 2 * DMODEL + h * DH;

    int lr = t >> 1, lc = (t & 1) * 64;      // row, half-offset (64 halves = 8 chunks)

    int it0 = (m0 >= 1152) ? 8 : 0;
    {
        const __half* g = qkv + (size_t)(m0 + lr) * LD + h * DH + lc;
        uint32_t s = qB + (lr * STR + lc) * 2;
        #pragma unroll
        for (int i = 0; i < 8; i++) cp16(s + i * 16, g + i * 8);
    }
    {
        const __half* g = kbase + (size_t)(it0 * 128 + lr) * LD + lc;
        uint32_t s = kB + (lr * STR + lc) * 2;
        #pragma unroll
        for (int i = 0; i < 8; i++) cp16(s + i * 16, g + i * 8);
    }
    cp_commit();
    cp_wait<0>();
    __syncthreads();

    float o[16][4];
    #pragma unroll
    for (int g = 0; g < 16; g++) { o[g][0] = o[g][1] = o[g][2] = o[g][3] = 0.f; }
    float mrow0 = -INFINITY, mrow1 = -INFINITY;
    float lsum0 = 0.f, lsum1 = 0.f;

    const float scale = 0.08838834764831845f;
    int me0 = m0 + wrow + gid;
    int me1 = me0 + 8;

    int lrow = (lane & 7) + ((lane >> 3) & 1) * 8;
    int lcol = (lane >> 4) * 8;
    int vrow = lane & 15, vcol = (lane >> 4) * 8;

    for (int it = it0; it <= mb; it++) {
        int n0 = it * 128;

        // prefetch V_it
        {
            const __half* g = vbase + (size_t)(n0 + lr) * LD + lc;
            uint32_t s = vB + (lr * STR + lc) * 2;
            #pragma unroll
            for (int i = 0; i < 8; i++) cp16(s + i * 16, g + i * 8);
            cp_commit();
        }

        // S = Q K^T  (fp16 mma, k16 x 8 steps)
        float s[16][4];
        #pragma unroll
        for (int g = 0; g < 16; g++) s[g][0] = s[g][1] = s[g][2] = s[g][3] = 0.f;

        #pragma unroll
        for (int kk = 0; kk < DH; kk += 16) {
            uint32_t af[4];
            ldsm4(af, qB + ((wrow + lrow) * STR + kk + lcol) * 2);
            #pragma unroll
            for (int g2 = 0; g2 < 8; g2++) {
                uint32_t bf[4];
                ldsm4(bf, kB + ((g2 * 16 + lrow) * STR + kk + lcol) * 2);
                mma_f16(s[2 * g2 + 0], af, bf[0], bf[2]);
                mma_f16(s[2 * g2 + 1], af, bf[1], bf[3]);
            }
        }
        __syncthreads();   // all warps done reading Ks

        // prefetch K_{it+1}
        if (it < mb) {
            const __half* g = kbase + (size_t)(n0 + 128 + lr) * LD + lc;
            uint32_t sa = kB + (lr * STR + lc) * 2;
            #pragma unroll
            for (int i = 0; i < 8; i++) cp16(sa + i * 16, g + i * 8);
        }
        cp_commit();

        // ---- online softmax ----
        float mx0 = -INFINITY, mx1 = -INFINITY;
        const float* bp0 = bias + (size_t)me0 * SEQ + n0 + 2 * t4;
        const float* bp1 = bias + (size_t)me1 * SEQ + n0 + 2 * t4;
        #pragma unroll
        for (int g = 0; g < 16; g++) {
            int nc = n0 + g * 8 + 2 * t4;
            float2 b0 = *(const float2*)(bp0 + g * 8);
            float2 b1 = *(const float2*)(bp1 + g * 8);
            bool a00 = (nc     <= me0) && !((me0 >= BOTTLE) && (nc     < BG));
            bool a01 = (nc + 1 <= me0) && !((me0 >= BOTTLE) && (nc + 1 < BG));
            bool a10 = (nc     <= me1) && !((me1 >= BOTTLE) && (nc     < BG));
            bool a11 = (nc + 1 <= me1) && !((me1 >= BOTTLE) && (nc + 1 < BG));
            s[g][0] = s[g][0] * scale + (a00 ? 0.f : -1e10f) + b0.x;
            s[g][1] = s[g][1] * scale + (a01 ? 0.f : -1e10f) + b0.y;
            s[g][2] = s[g][2] * scale + (a10 ? 0.f : -1e10f) + b1.x;
            s[g][3] = s[g][3] * scale + (a11 ? 0.f : -1e10f) + b1.y;
            mx0 = fmaxf(mx0, fmaxf(s[g][0], s[g][1]));
            mx1 = fmaxf(mx1, fmaxf(s[g][2], s[g][3]));
        }
        mx0 = fmaxf(mx0, __shfl_xor_sync(0xffffffffu, mx0, 1));
        mx0 = fmaxf(mx0, __shfl_xor_sync(0xffffffffu, mx0, 2));
        mx1 = fmaxf(mx1, __shfl_xor_sync(0xffffffffu, mx1, 1));
        mx1 = fmaxf(mx1, __shfl_xor_sync(0xffffffffu, mx1, 2));
        float mn0 = fmaxf(mrow0, mx0), mn1 = fmaxf(mrow1, mx1);
        float al0 = __expf(mrow0 - mn0), al1 = __expf(mrow1 - mn1);
        float rs0 = 0.f, rs1 = 0.f;
        #pragma unroll
        for (int g = 0; g < 16; g++) {
            s[g][0] = __expf(s[g][0] - mn0);
            s[g][1] = __expf(s[g][1] - mn0);
            s[g][2] = __expf(s[g][2] - mn1);
            s[g][3] = __expf(s[g][3] - mn1);
            rs0 += s[g][0] + s[g][1];
            rs1 += s[g][2] + s[g][3];
        }
        lsum0 = lsum0 * al0 + rs0;
        lsum1 = lsum1 * al1 + rs1;
        mrow0 = mn0; mrow1 = mn1;
        #pragma unroll
        for (int g = 0; g < 16; g++) {
            o[g][0] *= al0; o[g][1] *= al0; o[g][2] *= al1; o[g][3] *= al1;
        }

        cp_wait<1>();      // V_it complete
        __syncthreads();

        // O += P V  (P C-frag == A-frag layout: direct f16x2 pack, no shuffles)
        #pragma unroll
        for (int kt = 0; kt < 8; kt++) {
            uint32_t a[4];
            a[0] = packh2(s[2 * kt][0],     s[2 * kt][1]);
            a[1] = packh2(s[2 * kt][2],     s[2 * kt][3]);
            a[2] = packh2(s[2 * kt + 1][0], s[2 * kt + 1][1]);
            a[3] = packh2(s[2 * kt + 1][2], s[2 * kt + 1][3]);
            #pragma unroll
            for (int nf2 = 0; nf2 < 8; nf2++) {
                uint32_t bf[4];
                ldsm4t(bf, vB + ((kt * 16 + vrow) * STR + nf2 * 16 + vcol) * 2);
                mma_f16(o[2 * nf2 + 0], a, bf[0], bf[1]);
                mma_f16(o[2 * nf2 + 1], a, bf[2], bf[3]);
            }
        }
        cp_wait<0>();      // K_{it+1} complete
        __syncthreads();
    }

    lsum0 += __shfl_xor_sync(0xffffffffu, lsum0, 1);
    lsum0 += __shfl_xor_sync(0xffffffffu, lsum0, 2);
    lsum1 += __shfl_xor_sync(0xffffffffu, lsum1, 1);
    lsum1 += __shfl_xor_sync(0xffffffffu, lsum1, 2);
    float inv0 = 1.f / lsum0, inv1 = 1.f / lsum1;
    __half* o0 = att + (size_t)me0 * DMODEL + h * DH + 2 * t4;
    __half* o1 = att + (size_t)me1 * DMODEL + h * DH + 2 * t4;
    #pragma unroll
    for (int nf = 0; nf < 16; nf++) {
        *(uint32_t*)(o0 + nf * 8) = packh2(o[nf][0] * inv0, o[nf][1] * inv0);
        *(uint32_t*)(o1 + nf * 8) = packh2(o[nf][2] * inv1, o[nf][3] * inv1);
    }
}

extern "C" void kernel_launch(void* const* d_in, const int* in_sizes, int n_in,
                              void* d_out, int out_size) {
    (void)in_sizes; (void)n_in; (void)out_size;
    const float* x         = (const float*)d_in[0];
    const float* attn_bias = (const float*)d_in[1];
    const float* ln_scale  = (const float*)d_in[2];
    const float* ln_offset = (const float*)d_in[3];
    const float* Wq = (const float*)d_in[4];
    const float* Wk = (const float*)d_in[5];
    const float* Wv = (const float*)d_in[6];
    const float* Wo = (const float*)d_in[7];
    const float* W1 = (const float*)d_in[8];
    const float* b1 = (const float*)d_in[9];
    const float* W2 = (const float*)d_in[10];
    const float* b2 = (const float*)d_in[11];
    float* out = (float*)d_out;

    __half *xnh, *qkvh, *atth, *ffh, *wqkvT, *woT, *w1T, *w2T;
    cudaGetSymbolAddress((void**)&xnh,   g_xnh);
    cudaGetSymbolAddress((void**)&qkvh,  g_qkvh);
    cudaGetSymbolAddress((void**)&atth,  g_atth);
    cudaGetSymbolAddress((void**)&ffh,   g_ffh);
    cudaGetSymbolAddress((void**)&wqkvT, g_wqkvT);
    cudaGetSymbolAddress((void**)&woT,   g_woT);
    cudaGetSymbolAddress((void**)&w1T,   g_w1T);
    cudaGetSymbolAddress((void**)&w2T,   g_w2T);

    const int SM_HG = 4 * 2 * 128 * 40 * 2;     // 81920 B
    const int SM_FA = 3 * 128 * 136 * 2;         // 104448 B
    cudaFuncSetAttribute(hgemm<0, 1>, cudaFuncAttributeMaxDynamicSharedMemorySize, SM_HG);
    cudaFuncSetAttribute(hgemm<0, 0>, cudaFuncAttributeMaxDynamicSharedMemorySize, SM_HG);
    cudaFuncSetAttribute(hgemm<1, 1>, cudaFuncAttributeMaxDynamicSharedMemorySize, SM_HG);
    cudaFuncSetAttribute(hgemm<2, 0>, cudaFuncAttributeMaxDynamicSharedMemorySize, SM_HG);
    cudaFuncSetAttribute(flash_kernel, cudaFuncAttributeMaxDynamicSharedMemorySize, SM_FA);

    // 0. Transpose + fp16-convert weights -> [N,K]
    {
        dim3 b(32, 8);
        cvt_T_kernel<<<dim3(DMODEL / 32, DMODEL / 32), b>>>(Wq, wqkvT, DMODEL, DMODEL);
        cvt_T_kernel<<<dim3(DMODEL / 32, DMODEL / 32), b>>>(Wk, wqkvT + (size_t)DMODEL * DMODEL, DMODEL, DMODEL);
        cvt_T_kernel<<<dim3(DMODEL / 32, DMODEL / 32), b>>>(Wv, wqkvT + (size_t)2 * DMODEL * DMODEL, DMODEL, DMODEL);
        cvt_T_kernel<<<dim3(DMODEL / 32, DMODEL / 32), b>>>(Wo, woT, DMODEL, DMODEL);
        cvt_T_kernel<<<dim3(DFF / 32, DMODEL / 32), b>>>(W1, w1T, DMODEL, DFF);
        cvt_T_kernel<<<dim3(DMODEL / 32, DFF / 32), b>>>(W2, w2T, DFF, DMODEL);
    }

    // 1. LayerNorm -> xn half
    ln_kernel<<<SEQ, 256>>>(x, ln_scale, ln_offset, xnh);

    // 2. Fused QKV projection -> qkv half [SEQ, 6144]
    hgemm<0, 1><<<dim3(3 * DMODEL / 128, SEQ / 128), 256, SM_HG>>>(
        xnh, wqkvT, nullptr, nullptr, qkvh, DMODEL, 3 * DMODEL);

    // 3. RoPE (half, in place)
    rope_kernel<<<(SEQ * (DMODEL / 2) + 255) / 256, 256>>>(qkvh);

    // 4. FP16 flash attention -> att half
    flash_kernel<<<dim3(SEQ / 128, NH), 256, SM_FA>>>(qkvh, attn_bias, atth);

    // 5. attn_out = att @ Wo -> d_out (fp32)
    hgemm<0, 0><<<dim3(DMODEL / 128, SEQ / 128), 256, SM_HG>>>(
        atth, woT, nullptr, out, nullptr, DMODEL, DMODEL);

    // 6. ff = gelu(xn @ W1 + b1) -> half
    hgemm<1, 1><<<dim3(DFF / 128, SEQ / 128), 256, SM_HG>>>(
        xnh, w1T, b1, nullptr, ffh, DMODEL, DFF);

    // 7. out += ff @ W2 + b2
    hgemm<2, 0><<<dim3(DMODEL / 128, SEQ / 128), 256, SM_HG>>>(
        ffh, w2T, b2, out, nullptr, DFF, DMODEL);
}

// round 13
// speedup vs baseline: 13.6879x; 1.2115x over previous
#include <cuda_runtime.h>
#include <cuda_fp16.h>
#include <math.h>
#include <stdint.h>

#define SEQ 2048
#define DMODEL 2048
#define NH 16
#define DH 128
#define DFF 8192
#define BOTTLE 1088   /* BACKGROUND_LEN + STYLE_VECS_LEN */
#define BG 1024       /* BACKGROUND_LEN */

// -------- scratch (no allocations allowed) --------
__device__ __half g_xnh[(size_t)SEQ * DMODEL];
__device__ __half g_qkvh[(size_t)SEQ * 3 * DMODEL];
__device__ __half g_atth[(size_t)SEQ * DMODEL];
__device__ __half g_ffh[(size_t)SEQ * DFF];
// half weights, NATURAL [K, N] layouts (qkv fused along N)
__device__ __half g_wqkvh[(size_t)DMODEL * 3 * DMODEL];
__device__ __half g_woh[(size_t)DMODEL * DMODEL];
__device__ __half g_w1h[(size_t)DMODEL * DFF];
__device__ __half g_w2h[(size_t)DFF * DMODEL];

// -------- fp16 mma + ldmatrix --------
__device__ __forceinline__ void mma_f16(float c[4], const uint32_t a[4], const uint32_t b0,
                                        const uint32_t b1) {
    asm volatile(
        "mma.sync.aligned.m16n8k16.row.col.f32.f16.f16.f32 "
        "{%0,%1,%2,%3}, {%4,%5,%6,%7}, {%8,%9}, {%0,%1,%2,%3};\n"
        : "+f"(c[0]), "+f"(c[1]), "+f"(c[2]), "+f"(c[3])
        : "r"(a[0]), "r"(a[1]), "r"(a[2]), "r"(a[3]), "r"(b0), "r"(b1));
}
__device__ __forceinline__ void ldsm4(uint32_t* r, uint32_t addr) {
    asm volatile("ldmatrix.sync.aligned.m8n8.x4.shared.b16 {%0,%1,%2,%3}, [%4];"
                 : "=r"(r[0]), "=r"(r[1]), "=r"(r[2]), "=r"(r[3]) : "r"(addr));
}
__device__ __forceinline__ void ldsm4t(uint32_t* r, uint32_t addr) {
    asm volatile("ldmatrix.sync.aligned.m8n8.x4.trans.shared.b16 {%0,%1,%2,%3}, [%4];"
                 : "=r"(r[0]), "=r"(r[1]), "=r"(r[2]), "=r"(r[3]) : "r"(addr));
}
// pack two fp32 -> one fp16x2 register (lo = a, hi = b)
__device__ __forceinline__ uint32_t packh2(float a, float b) {
    uint32_t r;
    asm("cvt.rn.f16x2.f32 %0, %2, %1;" : "=r"(r) : "f"(a), "f"(b));
    return r;
}

// -------- cp.async helpers --------
__device__ __forceinline__ void cp16(uint32_t s, const void* g) {
    asm volatile("cp.async.cg.shared.global [%0], [%1], 16;" :: "r"(s), "l"(g));
}
__device__ __forceinline__ void cp_commit() { asm volatile("cp.async.commit_group;"); }
template <int N> __device__ __forceinline__ void cp_wait() {
    asm volatile("cp.async.wait_group %0;" :: "n"(N));
}

// -------- reductions --------
__device__ __forceinline__ float blockReduceSum(float val) {
    __shared__ float sh[8];
    __shared__ float res;
    int lane = threadIdx.x & 31, w = threadIdx.x >> 5;
    #pragma unroll
    for (int o = 16; o > 0; o >>= 1) val += __shfl_xor_sync(0xffffffffu, val, o);
    if (lane == 0) sh[w] = val;
    __syncthreads();
    if (threadIdx.x == 0) {
        float s = 0.f;
        #pragma unroll
        for (int i = 0; i < 8; i++) s += sh[i];
        res = s;
    }
    __syncthreads();
    float r = res;
    __syncthreads();
    return r;
}

// -------- streaming fp32 -> fp16 convert with column placement --------
// in: [rows, N] fp32.  out rows have leading dim ldo, starting column off.
__global__ void cvt_h_kernel(const float4* __restrict__ in, __half* __restrict__ out,
                             int N4, int ldo, int off, int total4) {
    int i = blockIdx.x * blockDim.x + threadIdx.x;
    if (i >= total4) return;
    int row = i / N4, c4 = i - row * N4;
    float4 v = in[i];
    uint2 o;
    o.x = packh2(v.x, v.y);
    o.y = packh2(v.z, v.w);
    *(uint2*)(out + (size_t)row * ldo + off + c4 * 4) = o;
}

// -------- LayerNorm (half output) --------
__global__ void ln_kernel(const float* __restrict__ x, const float* __restrict__ sc,
                          const float* __restrict__ of, __half* __restrict__ out) {
    int row = blockIdx.x;
    const float* xr = x + (size_t)row * DMODEL;
    __half* o = out + (size_t)row * DMODEL;
    float s = 0.f, s2 = 0.f;
    for (int i = threadIdx.x; i < DMODEL; i += blockDim.x) {
        float v = xr[i];
        s += v; s2 += v * v;
    }
    s  = blockReduceSum(s);
    s2 = blockReduceSum(s2);
    float mean = s / DMODEL;
    float var  = s2 / DMODEL - mean * mean;
    float r = rsqrtf(var + 1e-5f);
    for (int i = threadIdx.x; i < DMODEL; i += blockDim.x)
        o[i] = __float2half_rn(sc[i] * r * (xr[i] - mean) + of[i]);
}

// -------- RoPE on packed half qkv (q at 0, k at DMODEL) --------
__global__ void rope_kernel(__half* __restrict__ qkv) {
    int idx = blockIdx.x * blockDim.x + threadIdx.x;
    if (idx >= SEQ * (DMODEL / 2)) return;
    int t = idx / (DMODEL / 2);
    int r = idx % (DMODEL / 2);
    int h = r / (DH / 2);
    int i = r % (DH / 2);
    float inv = powf(10000.0f, -(float)(2 * i) / (float)DH);
    float ang = (float)t * inv;
    float s, c;
    sincosf(ang, &s, &c);
    size_t base = (size_t)t * (3 * DMODEL) + (size_t)h * DH + 2 * i;
    __half2* qp = (__half2*)(qkv + base);
    float2 q = __half22float2(*qp);
    *qp = __floats2half2_rn(q.x * c - q.y * s, q.y * c + q.x * s);
    __half2* kp = (__half2*)(qkv + base + DMODEL);
    float2 k = __half22float2(*kp);
    *kp = __floats2half2_rn(k.x * c - k.y * s, k.y * c + k.x * s);
}

__device__ __forceinline__ float gelu_f(float x) {
    float x3 = x * x * x;
    return 0.5f * x * (1.0f + tanhf(0.7978845608028654f * (x + 0.044715f * x3)));
}

// ============ FP16 tensor-core GEMM, B in NATURAL [K,N] (trans-ldmatrix) ============
// C[m,n] = sum_k A[m,k] * B[k,n]; A half [M,K] rm, B half [K,N] rm (ldb = N stride).
// EPI 0: v = acc   EPI 1: v = gelu(acc + bias[n])   EPI 2: v = C[idx] + acc + bias[n]
// OUTH: write half to Ch.
template <int EPI, int OUTH>
__global__ __launch_bounds__(256, 2)
void hgemm(const __half* __restrict__ A, const __half* __restrict__ B,
           const float* __restrict__ bias, float* __restrict__ C,
           __half* __restrict__ Ch, int K, int ldb, int ldc) {
    constexpr int S = 4, BK = 32;
    constexpr int LDA = 40;                  // A smem row halves (pad 8)
    constexpr int LDB = 136;                 // B smem row halves (pad 8)
    constexpr int ASTAGE = 128 * LDA;        // 5120 halves
    constexpr int BSTAGE = BK * LDB;         // 4352 halves

    extern __shared__ __half smh[];
    __half* Asm = smh;
    __half* Bsm = smh + S * ASTAGE;

    int t = threadIdx.x;
    int m0 = blockIdx.y * 128, n0 = blockIdx.x * 128;
    int lane = t & 31, warp = t >> 5;
    int wm = (warp >> 2) * 64;
    int wn = (warp & 3) * 32;
    int gid = lane >> 2, t4 = lane & 3;

    float acc[4][4][4];
    #pragma unroll
    for (int f = 0; f < 4; f++)
        #pragma unroll
        for (int g = 0; g < 4; g++)
            #pragma unroll
            for (int e = 0; e < 4; e++) acc[f][g][e] = 0.f;

    uint32_t aBase = (uint32_t)__cvta_generic_to_shared(Asm);
    uint32_t bBase = (uint32_t)__cvta_generic_to_shared(Bsm);

    int nt = K / BK;

    // A stage: 128 rows x 32 halves = 512 x 8-half chunks (16B each)
    // B stage: 32 rows x 128 halves = 512 x 8-half chunks
    auto load_stage = [&](int s, int kt) {
        int k0 = kt * BK;
        uint32_t as = aBase + s * ASTAGE * 2;
        uint32_t bs = bBase + s * BSTAGE * 2;
        #pragma unroll
        for (int i = 0; i < 2; i++) {
            int cid = t + i * 256;
            int row = cid >> 2, c = (cid & 3) * 8;
            cp16(as + (row * LDA + c) * 2, A + (size_t)(m0 + row) * K + k0 + c);
        }
        #pragma unroll
        for (int i = 0; i < 2; i++) {
            int cid = t + i * 256;
            int row = cid >> 4, c = (cid & 15) * 8;
            cp16(bs + (row * LDB + c) * 2, B + (size_t)(k0 + row) * ldb + n0 + c);
        }
    };

    #pragma unroll
    for (int s = 0; s < S - 1; s++) {
        if (s < nt) load_stage(s, s);
        cp_commit();
    }

    int lrow = (lane & 7) + ((lane >> 3) & 1) * 8;   // A ldsm row
    int lcol = (lane >> 4) * 8;                      // A ldsm k-offset
    int vrow = lane & 15, vcol = (lane >> 4) * 8;    // B trans-ldsm row/col

    for (int kt = 0; kt < nt; kt++) {
        cp_wait<S - 2>();
        __syncthreads();
        int nx = kt + S - 1;
        if (nx < nt) load_stage(nx & (S - 1), nx);
        cp_commit();

        uint32_t as = aBase + (kt & (S - 1)) * ASTAGE * 2;
        uint32_t bs = bBase + (kt & (S - 1)) * BSTAGE * 2;

        #pragma unroll
        for (int kk = 0; kk < BK; kk += 16) {
            uint32_t af[4][4];
            #pragma unroll
            for (int f = 0; f < 4; f++)
                ldsm4(af[f], as + ((wm + f * 16 + lrow) * LDA + kk + lcol) * 2);
            uint32_t bf[2][4];
            #pragma unroll
            for (int g2 = 0; g2 < 2; g2++)
                ldsm4t(bf[g2], bs + ((kk + vrow) * LDB + wn + g2 * 16 + vcol) * 2);
            #pragma unroll
            for (int f = 0; f < 4; f++) {
                mma_f16(acc[f][0], af[f], bf[0][0], bf[0][1]);
                mma_f16(acc[f][1], af[f], bf[0][2], bf[0][3]);
                mma_f16(acc[f][2], af[f], bf[1][0], bf[1][1]);
                mma_f16(acc[f][3], af[f], bf[1][2], bf[1][3]);
            }
        }
    }

    #pragma unroll
    for (int f = 0; f < 4; f++) {
        #pragma unroll
        for (int g = 0; g < 4; g++) {
            #pragma unroll
            for (int half = 0; half < 2; half++) {
                int m = m0 + wm + f * 16 + gid + half * 8;
                int n = n0 + wn + g * 8 + 2 * t4;
                float v0 = acc[f][g][half * 2 + 0];
                float v1 = acc[f][g][half * 2 + 1];
                size_t idx = (size_t)m * ldc + n;
                if (EPI == 1) {
                    v0 = gelu_f(v0 + bias[n]);
                    v1 = gelu_f(v1 + bias[n + 1]);
                } else if (EPI == 2) {
                    v0 = C[idx]     + v0 + bias[n];
                    v1 = C[idx + 1] + v1 + bias[n + 1];
                }
                if (OUTH) {
                    *(uint32_t*)(Ch + idx) = packh2(v0, v1);
                } else {
                    C[idx]     = v0;
                    C[idx + 1] = v1;
                }
            }
        }
    }
}

// ============ FP16 flash attention (m16n8k16 mma, ldmatrix, online softmax) ============
__global__ void __launch_bounds__(256, 1)
flash_kernel(const __half* __restrict__ qkv, const float* __restrict__ bias,
             __half* __restrict__ att) {
    constexpr int LD = 3 * DMODEL;
    constexpr int STR = 136;
    extern __shared__ __half smh[];
    __half* Qs = smh;
    __half* Ks = smh + 128 * STR;
    __half* Vs = smh + 2 * 128 * STR;
    uint32_t qB = (uint32_t)__cvta_generic_to_shared(Qs);
    uint32_t kB = (uint32_t)__cvta_generic_to_shared(Ks);
    uint32_t vB = (uint32_t)__cvta_generic_to_shared(Vs);

    int mb = blockIdx.x, h = blockIdx.y;
    int m0 = mb * 128;
    int t = threadIdx.x, lane = t & 31, warp = t >> 5;
    int gid = lane >> 2, t4 = lane & 3;
    int wrow = warp * 16;

    const __half* kbase = qkv + DMODEL + h * DH;
    const __half* vbase = qkv + 2 * DMODEL + h * DH;

    int lr = t >> 1, lc = (t & 1) * 64;

    int it0 = (m0 >= 1152) ? 8 : 0;
    {
        const __half* g = qkv + (size_t)(m0 + lr) * LD + h * DH + lc;
        uint32_t s = qB + (lr * STR + lc) * 2;
        #pragma unroll
        for (int i = 0; i < 8; i++) cp16(s + i * 16, g + i * 8);
    }
    {
        const __half* g = kbase + (size_t)(it0 * 128 + lr) * LD + lc;
        uint32_t s = kB + (lr * STR + lc) * 2;
        #pragma unroll
        for (int i = 0; i < 8; i++) cp16(s + i * 16, g + i * 8);
    }
    cp_commit();
    cp_wait<0>();
    __syncthreads();

    float o[16][4];
    #pragma unroll
    for (int g = 0; g < 16; g++) { o[g][0] = o[g][1] = o[g][2] = o[g][3] = 0.f; }
    float mrow0 = -INFINITY, mrow1 = -INFINITY;
    float lsum0 = 0.f, lsum1 = 0.f;

    const float scale = 0.08838834764831845f;
    int me0 = m0 + wrow + gid;
    int me1 = me0 + 8;

    int lrow = (lane & 7) + ((lane >> 3) & 1) * 8;
    int lcol = (lane >> 4) * 8;
    int vrow = lane & 15, vcol = (lane >> 4) * 8;

    for (int it = it0; it <= mb; it++) {
        int n0 = it * 128;

        {
            const __half* g = vbase + (size_t)(n0 + lr) * LD + lc;
            uint32_t s = vB + (lr * STR + lc) * 2;
            #pragma unroll
            for (int i = 0; i < 8; i++) cp16(s + i * 16, g + i * 8);
            cp_commit();
        }

        float s[16][4];
        #pragma unroll
        for (int g = 0; g < 16; g++) s[g][0] = s[g][1] = s[g][2] = s[g][3] = 0.f;

        #pragma unroll
        for (int kk = 0; kk < DH; kk += 16) {
            uint32_t af[4];
            ldsm4(af, qB + ((wrow + lrow) * STR + kk + lcol) * 2);
            #pragma unroll
            for (int g2 = 0; g2 < 8; g2++) {
                uint32_t bf[4];
                ldsm4(bf, kB + ((g2 * 16 + lrow) * STR + kk + lcol) * 2);
                mma_f16(s[2 * g2 + 0], af, bf[0], bf[2]);
                mma_f16(s[2 * g2 + 1], af, bf[1], bf[3]);
            }
        }
        __syncthreads();

        if (it < mb) {
            const __half* g = kbase + (size_t)(n0 + 128 + lr) * LD + lc;
            uint32_t sa = kB + (lr * STR + lc) * 2;
            #pragma unroll
            for (int i = 0; i < 8; i++) cp16(sa + i * 16, g + i * 8);
        }
        cp_commit();

        float mx0 = -INFINITY, mx1 = -INFINITY;
        const float* bp0 = bias + (size_t)me0 * SEQ + n0 + 2 * t4;
        const float* bp1 = bias + (size_t)me1 * SEQ + n0 + 2 * t4;
        #pragma unroll
        for (int g = 0; g < 16; g++) {
            int nc = n0 + g * 8 + 2 * t4;
            float2 b0 = *(const float2*)(bp0 + g * 8);
            float2 b1 = *(const float2*)(bp1 + g * 8);
            bool a00 = (nc     <= me0) && !((me0 >= BOTTLE) && (nc     < BG));
            bool a01 = (nc + 1 <= me0) && !((me0 >= BOTTLE) && (nc + 1 < BG));
            bool a10 = (nc     <= me1) && !((me1 >= BOTTLE) && (nc     < BG));
            bool a11 = (nc + 1 <= me1) && !((me1 >= BOTTLE) && (nc + 1 < BG));
            s[g][0] = s[g][0] * scale + (a00 ? 0.f : -1e10f) + b0.x;
            s[g][1] = s[g][1] * scale + (a01 ? 0.f : -1e10f) + b0.y;
            s[g][2] = s[g][2] * scale + (a10 ? 0.f : -1e10f) + b1.x;
            s[g][3] = s[g][3] * scale + (a11 ? 0.f : -1e10f) + b1.y;
            mx0 = fmaxf(mx0, fmaxf(s[g][0], s[g][1]));
            mx1 = fmaxf(mx1, fmaxf(s[g][2], s[g][3]));
        }
        mx0 = fmaxf(mx0, __shfl_xor_sync(0xffffffffu, mx0, 1));
        mx0 = fmaxf(mx0, __shfl_xor_sync(0xffffffffu, mx0, 2));
        mx1 = fmaxf(mx1, __shfl_xor_sync(0xffffffffu, mx1, 1));
        mx1 = fmaxf(mx1, __shfl_xor_sync(0xffffffffu, mx1, 2));
        float mn0 = fmaxf(mrow0, mx0), mn1 = fmaxf(mrow1, mx1);
        float al0 = __expf(mrow0 - mn0), al1 = __expf(mrow1 - mn1);
        float rs0 = 0.f, rs1 = 0.f;
        #pragma unroll
        for (int g = 0; g < 16; g++) {
            s[g][0] = __expf(s[g][0] - mn0);
            s[g][1] = __expf(s[g][1] - mn0);
            s[g][2] = __expf(s[g][2] - mn1);
            s[g][3] = __expf(s[g][3] - mn1);
            rs0 += s[g][0] + s[g][1];
            rs1 += s[g][2] + s[g][3];
        }
        lsum0 = lsum0 * al0 + rs0;
        lsum1 = lsum1 * al1 + rs1;
        mrow0 = mn0; mrow1 = mn1;
        #pragma unroll
        for (int g = 0; g < 16; g++) {
            o[g][0] *= al0; o[g][1] *= al0; o[g][2] *= al1; o[g][3] *= al1;
        }

        cp_wait<1>();
        __syncthreads();

        #pragma unroll
        for (int kt = 0; kt < 8; kt++) {
            uint32_t a[4];
            a[0] = packh2(s[2 * kt][0],     s[2 * kt][1]);
            a[1] = packh2(s[2 * kt][2],     s[2 * kt][3]);
            a[2] = packh2(s[2 * kt + 1][0], s[2 * kt + 1][1]);
            a[3] = packh2(s[2 * kt + 1][2], s[2 * kt + 1][3]);
            #pragma unroll
            for (int nf2 = 0; nf2 < 8; nf2++) {
                uint32_t bf[4];
                ldsm4t(bf, vB + ((kt * 16 + vrow) * STR + nf2 * 16 + vcol) * 2);
                mma_f16(o[2 * nf2 + 0], a, bf[0], bf[1]);
                mma_f16(o[2 * nf2 + 1], a, bf[2], bf[3]);
            }
        }
        cp_wait<0>();
        __syncthreads();
    }

    lsum0 += __shfl_xor_sync(0xffffffffu, lsum0, 1);
    lsum0 += __shfl_xor_sync(0xffffffffu, lsum0, 2);
    lsum1 += __shfl_xor_sync(0xffffffffu, lsum1, 1);
    lsum1 += __shfl_xor_sync(0xffffffffu, lsum1, 2);
    float inv0 = 1.f / lsum0, inv1 = 1.f / lsum1;
    __half* o0 = att + (size_t)me0 * DMODEL + h * DH + 2 * t4;
    __half* o1 = att + (size_t)me1 * DMODEL + h * DH + 2 * t4;
    #pragma unroll
    for (int nf = 0; nf < 16; nf++) {
        *(uint32_t*)(o0 + nf * 8) = packh2(o[nf][0] * inv0, o[nf][1] * inv0);
        *(uint32_t*)(o1 + nf * 8) = packh2(o[nf][2] * inv1, o[nf][3] * inv1);
    }
}

extern "C" void kernel_launch(void* const* d_in, const int* in_sizes, int n_in,
                              void* d_out, int out_size) {
    (void)in_sizes; (void)n_in; (void)out_size;
    const float* x         = (const float*)d_in[0];
    const float* attn_bias = (const float*)d_in[1];
    const float* ln_scale  = (const float*)d_in[2];
    const float* ln_offset = (const float*)d_in[3];
    const float* Wq = (const float*)d_in[4];
    const float* Wk = (const float*)d_in[5];
    const float* Wv = (const float*)d_in[6];
    const float* Wo = (const float*)d_in[7];
    const float* W1 = (const float*)d_in[8];
    const float* b1 = (const float*)d_in[9];
    const float* W2 = (const float*)d_in[10];
    const float* b2 = (const float*)d_in[11];
    float* out = (float*)d_out;

    __half *xnh, *qkvh, *atth, *ffh, *wqkvh, *woh, *w1h, *w2h;
    cudaGetSymbolAddress((void**)&xnh,   g_xnh);
    cudaGetSymbolAddress((void**)&qkvh,  g_qkvh);
    cudaGetSymbolAddress((void**)&atth,  g_atth);
    cudaGetSymbolAddress((void**)&ffh,   g_ffh);
    cudaGetSymbolAddress((void**)&wqkvh, g_wqkvh);
    cudaGetSymbolAddress((void**)&woh,   g_woh);
    cudaGetSymbolAddress((void**)&w1h,   g_w1h);
    cudaGetSymbolAddress((void**)&w2h,   g_w2h);

    const int SM_HG = 4 * (128 * 40 + 32 * 136) * 2;   // 75776 B
    const int SM_FA = 3 * 128 * 136 * 2;                // 104448 B
    cudaFuncSetAttribute(hgemm<0, 1>, cudaFuncAttributeMaxDynamicSharedMemorySize, SM_HG);
    cudaFuncSetAttribute(hgemm<0, 0>, cudaFuncAttributeMaxDynamicSharedMemorySize, SM_HG);
    cudaFuncSetAttribute(hgemm<1, 1>, cudaFuncAttributeMaxDynamicSharedMemorySize, SM_HG);
    cudaFuncSetAttribute(hgemm<2, 0>, cudaFuncAttributeMaxDynamicSharedMemorySize, SM_HG);
    cudaFuncSetAttribute(flash_kernel, cudaFuncAttributeMaxDynamicSharedMemorySize, SM_FA);

    // 0. Streaming fp16 conversion of weights (natural [K,N] layout; qkv fused along N)
    {
        int thr = 256;
        int n4a = DMODEL * DMODEL / 4;
        int n4b = DMODEL * DFF / 4;
        cvt_h_kernel<<<(n4a + thr - 1) / thr, thr>>>((const float4*)Wq, wqkvh, DMODEL / 4, 3 * DMODEL, 0,          n4a);
        cvt_h_kernel<<<(n4a + thr - 1) / thr, thr>>>((const float4*)Wk, wqkvh, DMODEL / 4, 3 * DMODEL, DMODEL,     n4a);
        cvt_h_kernel<<<(n4a + thr - 1) / thr, thr>>>((const float4*)Wv, wqkvh, DMODEL / 4, 3 * DMODEL, 2 * DMODEL, n4a);
        cvt_h_kernel<<<(n4a + thr - 1) / thr, thr>>>((const float4*)Wo, woh, DMODEL / 4, DMODEL, 0, n4a);
        cvt_h_kernel<<<(n4b + thr - 1) / thr, thr>>>((const float4*)W1, w1h, DFF / 4,    DFF,    0, n4b);
        cvt_h_kernel<<<(n4b + thr - 1) / thr, thr>>>((const float4*)W2, w2h, DMODEL / 4, DMODEL, 0, n4b);
    }

    // 1. LayerNorm -> xn half
    ln_kernel<<<SEQ, 256>>>(x, ln_scale, ln_offset, xnh);

    // 2. Fused QKV projection -> qkv half [SEQ, 6144]
    hgemm<0, 1><<<dim3(3 * DMODEL / 128, SEQ / 128), 256, SM_HG>>>(
        xnh, wqkvh, nullptr, nullptr, qkvh, DMODEL, 3 * DMODEL, 3 * DMODEL);

    // 3. RoPE (half, in place)
    rope_kernel<<<(SEQ * (DMODEL / 2) + 255) / 256, 256>>>(qkvh);

    // 4. FP16 flash attention -> att half
    flash_kernel<<<dim3(SEQ / 128, NH), 256, SM_FA>>>(qkvh, attn_bias, atth);

    // 5. attn_out = att @ Wo -> d_out (fp32)
    hgemm<0, 0><<<dim3(DMODEL / 128, SEQ / 128), 256, SM_HG>>>(
        atth, woh, nullptr, out, nullptr, DMODEL, DMODEL, DMODEL);

    // 6. ff = gelu(xn @ W1 + b1) -> half
    hgemm<1, 1><<<dim3(DFF / 128, SEQ / 128), 256, SM_HG>>>(
        xnh, w1h, b1, nullptr, ffh, DMODEL, DFF, DFF);

    // 7. out += ff @ W2 + b2
    hgemm<2, 0><<<dim3(DMODEL / 128, SEQ / 128), 256, SM_HG>>>(
        ffh, w2h, b2, out, nullptr, DFF, DMODEL, DMODEL);
}